// round 11
// baseline (speedup 1.0000x reference)
#include <cuda_runtime.h>
#include <math.h>
#include <stdint.h>

// ---------------- problem constants ----------------
#define TS     8
#define BATCH  16
#define NPG    4096
#define NEDGE  (TS*BATCH*32768)   // 4,194,304 edges (all timesteps, layer 1)
#define EPT    (32768*BATCH)      // 524288 edges per timestep
#define NG     (TS*BATCH)         // 128 graphs
#define EPSN   1e-5f
#define MAXN   524288

// ---------------- static device scratch ----------------
__device__ float g_S  [33554432];   // aggregated input (layer 3 only)
__device__ float g_AGG[67108864];   // gcn output Y = S*W + b
__device__ float g_X  [33554432];   // compacted layer input (normalized+gated)
__device__ float g_DINV[MAXN];
__device__ float g_SCORE[MAXN];
__device__ int   g_MAP [MAXN];
__device__ int   g_PERMG[262144];
__device__ float g_GATE [262144];
__device__ int   g_CNT[MAXN];
__device__ int   g_CUR[MAXN];
__device__ int   g_ROW[MAXN];
__device__ int   g_BSUM[1024];
__device__ int   g_CSRC[NEDGE];
__device__ float g_CW [NEDGE];
__device__ int   g_ESRC[2][NEDGE];
__device__ int   g_EDST[2][NEDGE];
__device__ int   g_ECNT[2];
__device__ float g_SP1[NG*256];     // invariant: zero between uses (finstats self-zeroes)
__device__ float g_SP2[NG*256];
__device__ float g_MU [NG*256];
__device__ float g_RS [NG*256];
__device__ float g_IPN;
__device__ float g_PMEAN[NG*256];
__device__ float g_PMAX [NG*256];

// ---------------- utility ----------------
__global__ void k_zeroi(int* a, int cnt){
    int i = blockIdx.x*blockDim.x + threadIdx.x;
    if (i < cnt) a[i] = 0;
}

// ---------------- layer-1 edge kernels: read edge_index directly ----------------
__global__ void k_count1(const int* __restrict__ ei){
    int idx = blockIdx.x*blockDim.x + threadIdx.x;
    if (idx >= NEDGE) return;
    int t = idx / EPT, e = idx % EPT;
    int d = ei[(size_t)t*2*EPT + EPT + e] + t*(BATCH*NPG);
    atomicAdd(&g_CNT[d], 1);
}
__global__ void k_fill1(const int* __restrict__ ei){
    int idx = blockIdx.x*blockDim.x + threadIdx.x;
    if (idx >= NEDGE) return;
    int t = idx / EPT, e = idx % EPT;
    int base = t*(BATCH*NPG);
    int s = ei[(size_t)t*2*EPT + e]       + base;
    int d = ei[(size_t)t*2*EPT + EPT + e] + base;
    int slot = g_ROW[d] + atomicAdd(&g_CUR[d], 1);
    g_CSRC[slot] = s;
    g_CW[slot]   = g_DINV[s]*g_DINV[d];
}
__global__ void k_remap1(const int* __restrict__ ei){
    int idx = blockIdx.x*blockDim.x + threadIdx.x;
    if (idx >= NEDGE) return;
    int t = idx / EPT, e = idx % EPT;
    int base = t*(BATCH*NPG);
    int s = g_MAP[ei[(size_t)t*2*EPT + e]       + base];
    int d = g_MAP[ei[(size_t)t*2*EPT + EPT + e] + base];
    if (s >= 0 && d >= 0){
        int p = atomicAdd(&g_ECNT[1], 1);
        g_ESRC[1][p] = s;
        g_EDST[1][p] = d;
        atomicAdd(&g_CNT[d], 1);
    }
}

// ---------------- CSR build ----------------
__global__ void k_scan1(int n){
    __shared__ int sh[512];
    int i = blockIdx.x*512 + threadIdx.x;
    int v = (i < n) ? g_CNT[i] : 0;
    sh[threadIdx.x] = v;
    __syncthreads();
    for (int st = 1; st < 512; st <<= 1){
        int t = (threadIdx.x >= st) ? sh[threadIdx.x - st] : 0;
        __syncthreads();
        sh[threadIdx.x] += t;
        __syncthreads();
    }
    if (i < n) g_ROW[i] = sh[threadIdx.x] - v;
    if (threadIdx.x == 511) g_BSUM[blockIdx.x] = sh[511];
}
__global__ void k_scan3d(int n){
    __shared__ int sh[512];
    int bid = blockIdx.x, tid = threadIdx.x;
    int acc = 0;
    for (int j = tid; j < bid; j += 512) acc += g_BSUM[j];
    sh[tid] = acc;
    __syncthreads();
    for (int st = 256; st > 0; st >>= 1){
        if (tid < st) sh[tid] += sh[tid + st];
        __syncthreads();
    }
    int base = sh[0];
    int i = bid*512 + tid;
    if (i < n){
        g_ROW[i] += base;
        g_CUR[i]  = 0;
        g_DINV[i] = rsqrtf(1.f + (float)g_CNT[i]);
    }
}

__global__ void k_fill(int cur){
    int e = blockIdx.x*blockDim.x + threadIdx.x;
    if (e >= g_ECNT[cur]) return;
    int s = g_ESRC[cur][e], d = g_EDST[cur][e];
    int slot = g_ROW[d] + atomicAdd(&g_CUR[d], 1);
    g_CSRC[slot] = s;
    g_CW[slot]   = g_DINV[s]*g_DINV[d];
}

// ---------------- standalone aggregate (layer 3 only) ----------------
__global__ void __launch_bounds__(256) k_aggregate(const float* __restrict__ X,
                                                   int ntot, int f){
    int node = (blockIdx.x*blockDim.x + threadIdx.x) >> 5;
    int lane = threadIdx.x & 31;
    if (node >= ntot) return;
    int fb = lane*4;
    if (fb >= f) return;
    int r0 = g_ROW[node];
    int cnt = g_CNT[node];
    int eend = r0 + cnt;
    float ax0=0.f, ay0=0.f, az0=0.f, aw0=0.f;
    float ax1=0.f, ay1=0.f, az1=0.f, aw1=0.f;
    float ax2=0.f, ay2=0.f, az2=0.f, aw2=0.f;
    float ax3=0.f, ay3=0.f, az3=0.f, aw3=0.f;
    int e = r0;
    for (; e + 3 < eend; e += 4){
        int s0 = g_CSRC[e],   s1 = g_CSRC[e+1], s2 = g_CSRC[e+2], s3 = g_CSRC[e+3];
        float w0 = g_CW[e],   w1 = g_CW[e+1],   w2 = g_CW[e+2],   w3 = g_CW[e+3];
        float4 v0 = *(const float4*)&X[(size_t)s0*f + fb];
        float4 v1 = *(const float4*)&X[(size_t)s1*f + fb];
        float4 v2 = *(const float4*)&X[(size_t)s2*f + fb];
        float4 v3 = *(const float4*)&X[(size_t)s3*f + fb];
        ax0 += w0*v0.x; ay0 += w0*v0.y; az0 += w0*v0.z; aw0 += w0*v0.w;
        ax1 += w1*v1.x; ay1 += w1*v1.y; az1 += w1*v1.z; aw1 += w1*v1.w;
        ax2 += w2*v2.x; ay2 += w2*v2.y; az2 += w2*v2.z; aw2 += w2*v2.w;
        ax3 += w3*v3.x; ay3 += w3*v3.y; az3 += w3*v3.z; aw3 += w3*v3.w;
    }
    for (; e + 1 < eend; e += 2){
        int s0 = g_CSRC[e],   s1 = g_CSRC[e+1];
        float w0 = g_CW[e],   w1 = g_CW[e+1];
        float4 v0 = *(const float4*)&X[(size_t)s0*f + fb];
        float4 v1 = *(const float4*)&X[(size_t)s1*f + fb];
        ax0 += w0*v0.x; ay0 += w0*v0.y; az0 += w0*v0.z; aw0 += w0*v0.w;
        ax1 += w1*v1.x; ay1 += w1*v1.y; az1 += w1*v1.z; aw1 += w1*v1.w;
    }
    if (e < eend){
        int s0 = g_CSRC[e];
        float w0 = g_CW[e];
        float4 v0 = *(const float4*)&X[(size_t)s0*f + fb];
        ax0 += w0*v0.x; ay0 += w0*v0.y; az0 += w0*v0.z; aw0 += w0*v0.w;
    }
    float di = g_DINV[node];
    float c = di*di;
    float4 sv = *(const float4*)&X[(size_t)node*f + fb];
    float4 o = { (ax0+ax1) + (ax2+ax3) + c*sv.x,
                 (ay0+ay1) + (ay2+ay3) + c*sv.y,
                 (az0+az1) + (az2+az3) + c*sv.z,
                 (aw0+aw1) + (aw2+aw3) + c*sv.w };
    *(float4*)&g_S[(size_t)node*f + fb] = o;
}

// ---------------- shared GEMM pieces ----------------
#define AS_STRIDE 36
#define BS_STRIDE 136
#define AFST 132                              // full-K A stride (fused kernel)
#define SMF_TOT ((2*128*AFST + 2*32*BS_STRIDE)*4)   // 169984 B
// unfused GEMM smem (layer 3)
#define SM_AH 0
#define SM_AL (128*AS_STRIDE)
#define SM_BH (2*128*AS_STRIDE)
#define SM_BL (2*128*AS_STRIDE + 32*BS_STRIDE)
#define SM_TOT ((2*128*AS_STRIDE + 2*32*BS_STRIDE)*4)

__device__ __forceinline__ float f2hi(float v){
    float h;
    asm("cvt.rna.tf32.f32 %0, %1;" : "=f"(h) : "f"(v));
    return h;
}
__device__ __forceinline__ void mma8(float* d, uint32_t a0, uint32_t a1, uint32_t a2, uint32_t a3,
                                     uint32_t b0, uint32_t b1){
    asm volatile("mma.sync.aligned.m16n8k8.row.col.f32.tf32.tf32.f32 "
        "{%0,%1,%2,%3}, {%4,%5,%6,%7}, {%8,%9}, {%0,%1,%2,%3};"
        : "+f"(d[0]), "+f"(d[1]), "+f"(d[2]), "+f"(d[3])
        : "r"(a0), "r"(a1), "r"(a2), "r"(a3), "r"(b0), "r"(b1));
}

// epilogue shared by both GEMM kernels
__device__ __forceinline__ void gemm_epilogue(float acc[2][8][4],
                                              const float* __restrict__ bias,
                                              float* __restrict__ C,
                                              int bm, int bn, int wm, int wn,
                                              int g4, int t4, int lane, int N, int npg){
    float ps[16], ps2[16];
    #pragma unroll
    for (int i = 0; i < 16; i++){ ps[i] = 0.f; ps2[i] = 0.f; }
    #pragma unroll
    for (int ma = 0; ma < 2; ma++){
        #pragma unroll
        for (int jn = 0; jn < 8; jn++){
            size_t row0 = (size_t)bm + wm + ma*16 + g4;
            int    colb = bn + wn + jn*8 + t4*2;
            float2 bv = *(const float2*)&bias[colb];
            float a0 = acc[ma][jn][0] + bv.x, a1 = acc[ma][jn][1] + bv.y;
            float a2 = acc[ma][jn][2] + bv.x, a3 = acc[ma][jn][3] + bv.y;
            float2 lo = { a0, a1 };
            float2 hi = { a2, a3 };
            *(float2*)&C[row0*N + colb]     = lo;
            *(float2*)&C[(row0+8)*N + colb] = hi;
            ps [jn*2+0] += a0 + a2;
            ps [jn*2+1] += a1 + a3;
            ps2[jn*2+0] += a0*a0 + a2*a2;
            ps2[jn*2+1] += a1*a1 + a3*a3;
        }
    }
    #pragma unroll
    for (int o = 4; o < 32; o <<= 1){
        #pragma unroll
        for (int i = 0; i < 16; i++){
            ps [i] += __shfl_xor_sync(0xFFFFFFFF, ps [i], o);
            ps2[i] += __shfl_xor_sync(0xFFFFFFFF, ps2[i], o);
        }
    }
    if (lane < 4){
        int g = bm / npg;
        #pragma unroll
        for (int i = 0; i < 16; i++){
            int colg = bn + wn + (i >> 1)*8 + t4*2 + (i & 1);
            atomicAdd(&g_SP1[g*256 + colg], ps[i]);
            atomicAdd(&g_SP2[g*256 + colg], ps2[i]);
        }
    }
}

// ---------------- FUSED aggregate + tf32-split GEMM (layers 1,2; grid.x==1) -----
// Phase 1: CSR-gather S rows into registers, split hi/lo into full-K smem A tile.
// Phase 2: chunked-B tf32-split MMA, bias + stats epilogue.
__global__ void __launch_bounds__(256) k_agg_gemm(const float* __restrict__ X,
                                                  const float* __restrict__ W,
                                                  const float* __restrict__ bias,
                                                  float* __restrict__ C,
                                                  int M, int N, int K, int npg){
    extern __shared__ float sm[];
    float* Ahf = sm;                       // [128][AFST] hi
    float* Alf = sm + 128*AFST;            // [128][AFST] lo
    float* Bh  = sm + 2*128*AFST;
    float* Bl  = Bh + 32*BS_STRIDE;
    const int tid = threadIdx.x, lane = tid & 31, wid = tid >> 5;
    const int wm = (wid >> 1)*32, wn = (wid & 1)*64;
    const int bm = blockIdx.y*128, bn = blockIdx.x*128;
    const int g4 = lane >> 2, t4 = lane & 3;
    const int K8 = ((K + 7)/8)*8;

    // ---- phase 1: gather 16 rows per warp ----
    int fb = lane*4;
    for (int rr = 0; rr < 16; rr++){
        int row = wid*16 + rr;
        if (fb < K8){
            float4 o = {0.f, 0.f, 0.f, 0.f};
            if (fb < K){
                int node = bm + row;
                int r0 = g_ROW[node];
                int eend = r0 + g_CNT[node];
                float ax0=0.f, ay0=0.f, az0=0.f, aw0=0.f;
                float ax1=0.f, ay1=0.f, az1=0.f, aw1=0.f;
                float ax2=0.f, ay2=0.f, az2=0.f, aw2=0.f;
                float ax3=0.f, ay3=0.f, az3=0.f, aw3=0.f;
                int e = r0;
                for (; e + 3 < eend; e += 4){
                    int s0 = g_CSRC[e],   s1 = g_CSRC[e+1], s2 = g_CSRC[e+2], s3 = g_CSRC[e+3];
                    float w0 = g_CW[e],   w1 = g_CW[e+1],   w2 = g_CW[e+2],   w3 = g_CW[e+3];
                    float4 v0 = *(const float4*)&X[(size_t)s0*K + fb];
                    float4 v1 = *(const float4*)&X[(size_t)s1*K + fb];
                    float4 v2 = *(const float4*)&X[(size_t)s2*K + fb];
                    float4 v3 = *(const float4*)&X[(size_t)s3*K + fb];
                    ax0 += w0*v0.x; ay0 += w0*v0.y; az0 += w0*v0.z; aw0 += w0*v0.w;
                    ax1 += w1*v1.x; ay1 += w1*v1.y; az1 += w1*v1.z; aw1 += w1*v1.w;
                    ax2 += w2*v2.x; ay2 += w2*v2.y; az2 += w2*v2.z; aw2 += w2*v2.w;
                    ax3 += w3*v3.x; ay3 += w3*v3.y; az3 += w3*v3.z; aw3 += w3*v3.w;
                }
                for (; e + 1 < eend; e += 2){
                    int s0 = g_CSRC[e],   s1 = g_CSRC[e+1];
                    float w0 = g_CW[e],   w1 = g_CW[e+1];
                    float4 v0 = *(const float4*)&X[(size_t)s0*K + fb];
                    float4 v1 = *(const float4*)&X[(size_t)s1*K + fb];
                    ax0 += w0*v0.x; ay0 += w0*v0.y; az0 += w0*v0.z; aw0 += w0*v0.w;
                    ax1 += w1*v1.x; ay1 += w1*v1.y; az1 += w1*v1.z; aw1 += w1*v1.w;
                }
                if (e < eend){
                    int s0 = g_CSRC[e];
                    float w0 = g_CW[e];
                    float4 v0 = *(const float4*)&X[(size_t)s0*K + fb];
                    ax0 += w0*v0.x; ay0 += w0*v0.y; az0 += w0*v0.z; aw0 += w0*v0.w;
                }
                float di = g_DINV[node];
                float c = di*di;
                float4 sv = *(const float4*)&X[(size_t)node*K + fb];
                o.x = (ax0+ax1) + (ax2+ax3) + c*sv.x;
                o.y = (ay0+ay1) + (ay2+ay3) + c*sv.y;
                o.z = (az0+az1) + (az2+az3) + c*sv.z;
                o.w = (aw0+aw1) + (aw2+aw3) + c*sv.w;
            }
            float hx = f2hi(o.x), hy = f2hi(o.y), hz = f2hi(o.z), hw = f2hi(o.w);
            float4 hi4 = { hx, hy, hz, hw };
            float4 lo4 = { o.x - hx, o.y - hy, o.z - hz, o.w - hw };
            *(float4*)&Ahf[row*AFST + fb] = hi4;
            *(float4*)&Alf[row*AFST + fb] = lo4;
        }
    }
    __syncthreads();

    // ---- phase 2: chunked-B MMA over full-K A tile ----
    float acc[2][8][4] = {};
    const int nch = (K8 + 31)/32;
    for (int kc = 0; kc < nch; kc++){
        const int k0 = kc*32;
        const int kend = min(32, K8 - k0);
        if (kc > 0) __syncthreads();
        #pragma unroll
        for (int it = 0; it < 16; it++){
            int idx = it*256 + tid;
            int nc = idx & 127, kr = idx >> 7;
            int kg = k0 + kr;
            float v = (kg < K) ? W[(size_t)kg*N + bn + nc] : 0.f;
            float h = f2hi(v);
            Bh[kr*BS_STRIDE + nc] = h;
            Bl[kr*BS_STRIDE + nc] = v - h;
        }
        __syncthreads();

        for (int kk = 0; kk < kend; kk += 8){
            uint32_t ah[2][4], al[2][4];
            #pragma unroll
            for (int ma = 0; ma < 2; ma++){
                int r0 = (wm + ma*16 + g4)*AFST;
                int c0 = k0 + kk + t4;
                ah[ma][0] = __float_as_uint(Ahf[r0 + c0]);
                ah[ma][1] = __float_as_uint(Ahf[r0 + 8*AFST + c0]);
                ah[ma][2] = __float_as_uint(Ahf[r0 + c0 + 4]);
                ah[ma][3] = __float_as_uint(Ahf[r0 + 8*AFST + c0 + 4]);
                al[ma][0] = __float_as_uint(Alf[r0 + c0]);
                al[ma][1] = __float_as_uint(Alf[r0 + 8*AFST + c0]);
                al[ma][2] = __float_as_uint(Alf[r0 + c0 + 4]);
                al[ma][3] = __float_as_uint(Alf[r0 + 8*AFST + c0 + 4]);
            }
            #pragma unroll
            for (int jn = 0; jn < 8; jn++){
                int col = wn + jn*8 + g4;
                uint32_t bh0 = __float_as_uint(Bh[(kk + t4)*BS_STRIDE + col]);
                uint32_t bh1 = __float_as_uint(Bh[(kk + 4 + t4)*BS_STRIDE + col]);
                uint32_t bl0 = __float_as_uint(Bl[(kk + t4)*BS_STRIDE + col]);
                uint32_t bl1 = __float_as_uint(Bl[(kk + 4 + t4)*BS_STRIDE + col]);
                #pragma unroll
                for (int ma = 0; ma < 2; ma++){
                    mma8(acc[ma][jn], ah[ma][0], ah[ma][1], ah[ma][2], ah[ma][3], bh0, bh1);
                    mma8(acc[ma][jn], al[ma][0], al[ma][1], al[ma][2], al[ma][3], bh0, bh1);
                    mma8(acc[ma][jn], ah[ma][0], ah[ma][1], ah[ma][2], ah[ma][3], bl0, bl1);
                }
            }
        }
    }
    gemm_epilogue(acc, bias, C, bm, bn, wm, wn, g4, t4, lane, N, npg);
}

// ---------------- unfused tf32-split GEMM (layer 3) -----------------------------
__global__ void __launch_bounds__(256) k_gemm_tc(const float* __restrict__ A,
                                                 const float* __restrict__ W,
                                                 const float* __restrict__ bias,
                                                 float* __restrict__ C,
                                                 int M, int N, int K, int npg){
    extern __shared__ float sm[];
    float* Ah = sm + SM_AH/1;
    float* Al = sm + SM_AL;
    float* Bh = sm + SM_BH;
    float* Bl = sm + SM_BL;
    const int tid = threadIdx.x, lane = tid & 31, wid = tid >> 5;
    const int wm = (wid >> 1)*32, wn = (wid & 1)*64;
    const int bm = blockIdx.y*128, bn = blockIdx.x*128;
    const int g4 = lane >> 2, t4 = lane & 3;

    float acc[2][8][4] = {};

    const int K8 = ((K + 7)/8)*8;
    const int nch = (K8 + 31)/32;
    for (int kc = 0; kc < nch; kc++){
        const int k0 = kc*32;
        const int kend = min(32, K8 - k0);
        #pragma unroll
        for (int it = 0; it < 16; it++){
            int idx = it*256 + tid;
            int col = idx & 31, row = idx >> 5;
            int kg = k0 + col;
            float v = (kg < K) ? A[(size_t)(bm+row)*K + kg] : 0.f;
            float h = f2hi(v);
            Ah[row*AS_STRIDE + col] = h;
            Al[row*AS_STRIDE + col] = v - h;
        }
        #pragma unroll
        for (int it = 0; it < 16; it++){
            int idx = it*256 + tid;
            int nc = idx & 127, kr = idx >> 7;
            int kg = k0 + kr;
            float v = (kg < K) ? W[(size_t)kg*N + bn + nc] : 0.f;
            float h = f2hi(v);
            Bh[kr*BS_STRIDE + nc] = h;
            Bl[kr*BS_STRIDE + nc] = v - h;
        }
        __syncthreads();

        for (int kk = 0; kk < kend; kk += 8){
            uint32_t ah[2][4], al[2][4];
            #pragma unroll
            for (int ma = 0; ma < 2; ma++){
                int r0 = (wm + ma*16 + g4)*AS_STRIDE;
                int c0 = kk + t4;
                ah[ma][0] = __float_as_uint(Ah[r0 + c0]);
                ah[ma][1] = __float_as_uint(Ah[r0 + 8*AS_STRIDE + c0]);
                ah[ma][2] = __float_as_uint(Ah[r0 + c0 + 4]);
                ah[ma][3] = __float_as_uint(Ah[r0 + 8*AS_STRIDE + c0 + 4]);
                al[ma][0] = __float_as_uint(Al[r0 + c0]);
                al[ma][1] = __float_as_uint(Al[r0 + 8*AS_STRIDE + c0]);
                al[ma][2] = __float_as_uint(Al[r0 + c0 + 4]);
                al[ma][3] = __float_as_uint(Al[r0 + 8*AS_STRIDE + c0 + 4]);
            }
            #pragma unroll
            for (int jn = 0; jn < 8; jn++){
                int col = wn + jn*8 + g4;
                uint32_t bh0 = __float_as_uint(Bh[(kk + t4)*BS_STRIDE + col]);
                uint32_t bh1 = __float_as_uint(Bh[(kk + 4 + t4)*BS_STRIDE + col]);
                uint32_t bl0 = __float_as_uint(Bl[(kk + t4)*BS_STRIDE + col]);
                uint32_t bl1 = __float_as_uint(Bl[(kk + 4 + t4)*BS_STRIDE + col]);
                #pragma unroll
                for (int ma = 0; ma < 2; ma++){
                    mma8(acc[ma][jn], ah[ma][0], ah[ma][1], ah[ma][2], ah[ma][3], bh0, bh1);
                    mma8(acc[ma][jn], al[ma][0], al[ma][1], al[ma][2], al[ma][3], bh0, bh1);
                    mma8(acc[ma][jn], ah[ma][0], ah[ma][1], ah[ma][2], ah[ma][3], bl0, bl1);
                }
            }
        }
        __syncthreads();
    }
    gemm_epilogue(acc, bias, C, bm, bn, wm, wn, g4, t4, lane, N, npg);
}

// ---------------- finalize stats (+ pw norm), self-zero partials ----------------
__global__ void k_finstats(const float* __restrict__ ga, const float* __restrict__ pw,
                           int n, int f){
    int i = blockIdx.x*blockDim.x + threadIdx.x;
    if (i < NG*256){
        int fi = i & 255;
        if (fi < f){
            float s = g_SP1[i], s2 = g_SP2[i];
            g_SP1[i] = 0.f; g_SP2[i] = 0.f;
            float inv_n = 1.f/(float)n;
            float mu = s*inv_n;
            float m2 = s2*inv_n;
            float a = ga[fi];
            float var = m2 - mu*mu*a*(2.f - a);
            g_MU[i] = mu;
            g_RS[i] = rsqrtf(fmaxf(var, 0.f) + EPSN);
        }
    }
    if (blockIdx.x == 0){
        __shared__ float sh[256];
        float v = (threadIdx.x < f) ? pw[threadIdx.x] : 0.f;
        sh[threadIdx.x] = v*v;
        __syncthreads();
        for (int st = 128; st > 0; st >>= 1){
            if (threadIdx.x < st) sh[threadIdx.x] += sh[threadIdx.x + st];
            __syncthreads();
        }
        if (threadIdx.x == 0) g_IPN = rsqrtf(sh[0]);
    }
}

// ---------------- score: norm+relu on the fly, warp per node ----------------
__global__ void k_score(const float* __restrict__ gw, const float* __restrict__ gb,
                        const float* __restrict__ ga, const float* __restrict__ pw,
                        int ntot, int n, int f){
    int node = (blockIdx.x*blockDim.x + threadIdx.x) >> 5;
    int lane = threadIdx.x & 31;
    if (node >= ntot) return;
    int g = node / n;
    float dot = 0.f;
    for (int fc = lane*4; fc < f; fc += 128){
        float4 v  = *(const float4*)&g_AGG[(size_t)node*f + fc];
        float4 mu = *(const float4*)&g_MU[g*256 + fc];
        float4 rs = *(const float4*)&g_RS[g*256 + fc];
        float4 w  = *(const float4*)&gw[fc];
        float4 b  = *(const float4*)&gb[fc];
        float4 a  = *(const float4*)&ga[fc];
        float4 p  = *(const float4*)&pw[fc];
        float x0 = fmaxf(w.x*(v.x - a.x*mu.x)*rs.x + b.x, 0.f);
        float x1 = fmaxf(w.y*(v.y - a.y*mu.y)*rs.y + b.y, 0.f);
        float x2 = fmaxf(w.z*(v.z - a.z*mu.z)*rs.z + b.z, 0.f);
        float x3 = fmaxf(w.w*(v.w - a.w*mu.w)*rs.w + b.w, 0.f);
        dot += x0*p.x + x1*p.y + x2*p.z + x3*p.w;
    }
    #pragma unroll
    for (int o = 16; o > 0; o >>= 1) dot += __shfl_xor_sync(0xFFFFFFFF, dot, o);
    if (lane == 0) g_SCORE[node] = tanhf(dot*g_IPN);
}

// ---------------- per-graph exact top-k ----------------
__global__ void k_topk(int n, int k, int nxt){
    __shared__ unsigned keys[4096];
    __shared__ int hist[256];
    __shared__ unsigned sh_prefix;
    __shared__ int sh_rem;
    __shared__ int sg[512], se[512];
    __shared__ int base_g, base_e;

    int g = blockIdx.x;
    int tid = threadIdx.x;
    if (g == 0 && tid == 0) g_ECNT[nxt] = 0;
    const float* sc = g_SCORE + (size_t)g*n;

    for (int i = tid; i < n; i += blockDim.x){
        unsigned u = __float_as_uint(sc[i]);
        u = (u & 0x80000000u) ? ~u : (u | 0x80000000u);
        keys[i] = u;
    }
    if (tid == 0){ sh_prefix = 0u; sh_rem = k; }
    __syncthreads();

    for (int shift = 24; shift >= 0; shift -= 8){
        for (int i = tid; i < 256; i += blockDim.x) hist[i] = 0;
        __syncthreads();
        unsigned pmask = (shift == 24) ? 0u : (0xFFFFFFFFu << (shift + 8));
        unsigned pref = sh_prefix;
        for (int i = tid; i < n; i += blockDim.x){
            unsigned u = keys[i];
            if ((u & pmask) == pref) atomicAdd(&hist[(u >> shift) & 0xFF], 1);
        }
        __syncthreads();
        if (tid == 0){
            int rem = sh_rem, b;
            for (b = 255; b >= 0; b--){
                if (rem <= hist[b]) break;
                rem -= hist[b];
            }
            sh_prefix |= ((unsigned)b) << shift;
            sh_rem = rem;
        }
        __syncthreads();
    }
    unsigned thr = sh_prefix;
    int need = sh_rem;
    if (tid == 0){ base_g = 0; base_e = 0; }
    __syncthreads();

    for (int c0 = 0; c0 < n; c0 += blockDim.x){
        int i = c0 + tid;
        int gf = 0, ef = 0;
        if (i < n){
            unsigned u = keys[i];
            gf = (u > thr);
            ef = (u == thr);
        }
        sg[tid] = gf; se[tid] = ef;
        __syncthreads();
        for (int st = 1; st < blockDim.x; st <<= 1){
            int vg = 0, ve = 0;
            if (tid >= st){ vg = sg[tid-st]; ve = se[tid-st]; }
            __syncthreads();
            sg[tid] += vg; se[tid] += ve;
            __syncthreads();
        }
        if (i < n){
            int g_before = base_g + sg[tid] - gf;
            int e_before = base_e + se[tid] - ef;
            bool kept = gf || (ef && (e_before < need));
            int oldg = g*n + i;
            if (kept){
                int newlocal = g_before + min(e_before, need);
                int newglobal = g*k + newlocal;
                g_MAP[oldg]        = newglobal;
                g_PERMG[newglobal] = oldg;
                g_GATE[newglobal]  = sc[i];
            } else {
                g_MAP[oldg] = -1;
            }
        }
        __syncthreads();
        if (tid == 0){ base_g += sg[blockDim.x-1]; base_e += se[blockDim.x-1]; }
        __syncthreads();
    }
}

// ---------------- gather kept nodes with fused norm+relu+gate (layers 1,2) ------
__global__ void k_gather_norm(const float* __restrict__ gw, const float* __restrict__ gb,
                              const float* __restrict__ ga,
                              int tot_new, int n, int f){
    int per = f >> 2;
    size_t idx = (size_t)blockIdx.x*blockDim.x + threadIdx.x;
    if (idx >= (size_t)tot_new*per) return;
    int j  = (int)(idx / per);
    int fc = (int)(idx % per)*4;
    int old = g_PERMG[j];
    int g = old / n;
    float gv = g_GATE[j];
    float4 v  = *(const float4*)&g_AGG[(size_t)old*f + fc];
    float4 mu = *(const float4*)&g_MU[g*256 + fc];
    float4 rs = *(const float4*)&g_RS[g*256 + fc];
    float4 w  = *(const float4*)&gw[fc];
    float4 b  = *(const float4*)&gb[fc];
    float4 a  = *(const float4*)&ga[fc];
    float4 o;
    o.x = fmaxf(w.x*(v.x - a.x*mu.x)*rs.x + b.x, 0.f)*gv;
    o.y = fmaxf(w.y*(v.y - a.y*mu.y)*rs.y + b.y, 0.f)*gv;
    o.z = fmaxf(w.z*(v.z - a.z*mu.z)*rs.z + b.z, 0.f)*gv;
    o.w = fmaxf(w.w*(v.w - a.w*mu.w)*rs.w + b.w, 0.f)*gv;
    *(float4*)&g_X[(size_t)j*f + fc] = o;
}

// ---------------- generic remap (layer 2) ----------------
__global__ void k_remap(int cur){
    int e = blockIdx.x*blockDim.x + threadIdx.x;
    if (e >= g_ECNT[cur]) return;
    int s = g_MAP[g_ESRC[cur][e]];
    int d = g_MAP[g_EDST[cur][e]];
    if (s >= 0 && d >= 0){
        int p = atomicAdd(&g_ECNT[cur^1], 1);
        g_ESRC[cur^1][p] = s;
        g_EDST[cur^1][p] = d;
        atomicAdd(&g_CNT[d], 1);
    }
}

// ---------------- fused L3 gather + readout ----------------
__global__ void k_readout(const float* __restrict__ gw, const float* __restrict__ gb,
                          const float* __restrict__ ga, int n){
    int gg = blockIdx.x;
    int f  = threadIdx.x;   // 256
    float w = gw[f], b = gb[f], a = ga[f];
    float mu = g_MU[gg*256 + f], rs = g_RS[gg*256 + f];
    float s = 0.f, mx = -INFINITY;
    for (int i = 0; i < 512; i++){
        int j = gg*512 + i;
        int old = g_PERMG[j];
        float gv = g_GATE[j];
        float v = g_AGG[(size_t)old*256 + f];
        float x = fmaxf(w*(v - a*mu)*rs + b, 0.f)*gv;
        s += x;
        mx = fmaxf(mx, x);
    }
    g_PMEAN[gg*256 + f] = s*(1.f/512.f);
    g_PMAX [gg*256 + f] = mx;
}

__global__ void k_final(float* __restrict__ out){
    int idx = blockIdx.x*blockDim.x + threadIdx.x;
    if (idx >= BATCH*512) return;
    int b = idx / 512, c = idx % 512;
    float acc = 0.f;
    if (c < 256){
        for (int t = 0; t < TS; t++) acc += g_PMEAN[(t*BATCH + b)*256 + c];
    } else {
        for (int t = 0; t < TS; t++) acc += g_PMAX[(t*BATCH + b)*256 + (c-256)];
    }
    out[idx] = acc*(1.f/(float)TS);
}

// ---------------- host orchestration ----------------
extern "C" void kernel_launch(void* const* d_in, const int* in_sizes, int n_in,
                              void* d_out, int out_size){
    const float* x_seq = (const float*)d_in[0];
    const int*   ei    = (const int*)  d_in[1];
    const float* W [3] = {(const float*)d_in[2],  (const float*)d_in[4],  (const float*)d_in[6]};
    const float* bb[3] = {(const float*)d_in[3],  (const float*)d_in[5],  (const float*)d_in[7]};
    const float* gw[3] = {(const float*)d_in[8],  (const float*)d_in[11], (const float*)d_in[14]};
    const float* gb[3] = {(const float*)d_in[9],  (const float*)d_in[12], (const float*)d_in[15]};
    const float* ga[3] = {(const float*)d_in[10], (const float*)d_in[13], (const float*)d_in[16]};
    const float* pw[3] = {(const float*)d_in[17], (const float*)d_in[18], (const float*)d_in[19]};
    float* out = (float*)d_out;

    float *pS, *pX, *pAGG;
    int *pCNT;
    cudaGetSymbolAddress((void**)&pS,   g_S);
    cudaGetSymbolAddress((void**)&pX,   g_X);
    cudaGetSymbolAddress((void**)&pAGG, g_AGG);
    cudaGetSymbolAddress((void**)&pCNT, g_CNT);

    cudaFuncSetAttribute(k_gemm_tc,  cudaFuncAttributeMaxDynamicSharedMemorySize, SM_TOT);
    cudaFuncSetAttribute(k_agg_gemm, cudaFuncAttributeMaxDynamicSharedMemorySize, SMF_TOT);

    const int nin [3] = {4096, 2048, 1024};
    const int nk  [3] = {2048, 1024, 512};
    const int fin [3] = {100, 128, 128};
    const int fout[3] = {128, 128, 256};

    k_zeroi<<<(NG*NPG + 255)/256, 256>>>(pCNT, NG*NPG);
    k_count1<<<NEDGE/256, 256>>>(ei);

    const float* A = x_seq;
    for (int l = 0; l < 3; l++){
        int n = nin[l], k = nk[l], fi = fin[l], fo = fout[l];
        int ntot = NG * n;
        int cur = l & 1, nxt = cur ^ 1;
        int nb = ntot / 512;

        k_scan1 <<<nb, 512>>>(ntot);
        k_scan3d<<<nb, 512>>>(ntot);
        if (l == 0) k_fill1<<<NEDGE/256, 256>>>(ei);
        else        k_fill <<<NEDGE/256, 256>>>(cur);

        if (l < 2){
            // fused aggregate + GEMM (grid.x == 1 since fo == 128)
            k_agg_gemm<<<dim3(fo/128, ntot/128), 256, SMF_TOT>>>(A, W[l], bb[l], pAGG, ntot, fo, fi, n);
        } else {
            k_aggregate<<<ntot/8, 256>>>(A, ntot, fi);
            k_gemm_tc<<<dim3(fo/128, ntot/128), 256, SM_TOT>>>(pS, W[l], bb[l], pAGG, ntot, fo, fi, n);
        }

        k_finstats<<<(NG*256 + 255)/256, 256>>>(ga[l], pw[l], n, fo);
        k_score<<<ntot/8, 256>>>(gw[l], gb[l], ga[l], pw[l], ntot, n, fo);

        k_topk<<<NG, 512>>>(n, k, nxt);
        int tot_new = NG * k;
        if (l < 2){
            k_zeroi<<<(tot_new + 255)/256, 256>>>(pCNT, tot_new);
            if (l == 0) k_remap1<<<NEDGE/256, 256>>>(ei);
            else        k_remap <<<NEDGE/256, 256>>>(cur);
            k_gather_norm<<<(int)(((size_t)tot_new*(fo/4) + 255)/256), 256>>>(gw[l], gb[l], ga[l], tot_new, n, fo);
            A = pX;
        }
    }

    k_readout<<<NG, 256>>>(gw[2], gb[2], ga[2], nin[2]);
    k_final<<<(BATCH*512 + 255)/256, 256>>>(out);
}

// round 12
// speedup vs baseline: 1.3034x; 1.3034x over previous
#include <cuda_runtime.h>
#include <math.h>
#include <stdint.h>

// ---------------- problem constants ----------------
#define TS     8
#define BATCH  16
#define NPG    4096
#define NEDGE  (TS*BATCH*32768)   // 4,194,304 edges (all timesteps, layer 1)
#define NG     (TS*BATCH)         // 128 graphs
#define EPSN   1e-5f
#define MAXN   524288

// ---------------- static device scratch ----------------
__device__ float g_S  [67108864];   // aggregated input  S = A_norm * X
__device__ float g_AGG[67108864];   // gcn output Y = S*W + b
__device__ float g_X  [33554432];   // compacted layer input (normalized+gated)
__device__ float g_DINV[MAXN];
__device__ float g_SCORE[MAXN];
__device__ int   g_MAP [MAXN];
__device__ int   g_PERMG[262144];
__device__ float g_GATE [262144];
__device__ int   g_CNT[MAXN];
__device__ int   g_CUR[MAXN];
__device__ int   g_ROW[MAXN];
__device__ int   g_BSUM[1024];
__device__ int   g_CSRC[NEDGE];
__device__ float g_CW [NEDGE];
__device__ int   g_ESRC[2][NEDGE];
__device__ int   g_EDST[2][NEDGE];
__device__ int   g_ECNT[2];
__device__ float g_SP1[NG*256];
__device__ float g_SP2[NG*256];
__device__ float g_MU [NG*256];
__device__ float g_RS [NG*256];
__device__ float g_IPN;
__device__ float g_PMEAN[NG*256];
__device__ float g_PMAX [NG*256];

// ---------------- utility ----------------
__global__ void k_zero2i(int* a, int* b, int cnt){
    int i = blockIdx.x*blockDim.x + threadIdx.x;
    if (i < cnt){ a[i] = 0; b[i] = 0; }
}
__global__ void k_zeroSP(){
    int i = blockIdx.x*blockDim.x + threadIdx.x;
    if (i < NG*256){ g_SP1[i] = 0.f; g_SP2[i] = 0.f; }
}

__global__ void k_edge_init(const int* __restrict__ ei){
    int idx = blockIdx.x*blockDim.x + threadIdx.x;
    if (idx == 0){ g_ECNT[0] = NEDGE; g_ECNT[1] = 0; }
    if (idx >= NEDGE) return;
    const int E = 32768*BATCH;
    int t = idx / E, e = idx % E;
    int base = t * (BATCH*NPG);
    int s = ei[(size_t)t*2*E + e]     + base;
    int d = ei[(size_t)t*2*E + E + e] + base;
    g_ESRC[0][idx] = s;
    g_EDST[0][idx] = d;
    atomicAdd(&g_CNT[d], 1);
}

// ---------------- CSR build ----------------
__global__ void k_scan1(int n){
    __shared__ int sh[512];
    int i = blockIdx.x*512 + threadIdx.x;
    int v = (i < n) ? g_CNT[i] : 0;
    sh[threadIdx.x] = v;
    __syncthreads();
    for (int st = 1; st < 512; st <<= 1){
        int t = (threadIdx.x >= st) ? sh[threadIdx.x - st] : 0;
        __syncthreads();
        sh[threadIdx.x] += t;
        __syncthreads();
    }
    if (i < n) g_ROW[i] = sh[threadIdx.x] - v;
    if (threadIdx.x == 511) g_BSUM[blockIdx.x] = sh[511];
}
__global__ void k_scan3d(int n){
    __shared__ int sh[512];
    int bid = blockIdx.x, tid = threadIdx.x;
    int acc = 0;
    for (int j = tid; j < bid; j += 512) acc += g_BSUM[j];
    sh[tid] = acc;
    __syncthreads();
    for (int st = 256; st > 0; st >>= 1){
        if (tid < st) sh[tid] += sh[tid + st];
        __syncthreads();
    }
    int base = sh[0];
    int i = bid*512 + tid;
    if (i < n){
        g_ROW[i] += base;
        g_DINV[i] = rsqrtf(1.f + (float)g_CNT[i]);
    }
}

__global__ void k_fill(int cur){
    int e = blockIdx.x*blockDim.x + threadIdx.x;
    if (e >= g_ECNT[cur]) return;
    int s = g_ESRC[cur][e], d = g_EDST[cur][e];
    int slot = g_ROW[d] + atomicAdd(&g_CUR[d], 1);
    g_CSRC[slot] = s;
    g_CW[slot]   = g_DINV[s]*g_DINV[d];
}

// ---------------- aggregate-first: S[d] = sum w_e X[s] + dinv[d]^2 X[d] ----------
__global__ void k_aggregate(const float* __restrict__ X, int ntot, int f, int wpn){
    int gw = (blockIdx.x*blockDim.x + threadIdx.x) >> 5;
    int lane = threadIdx.x & 31;
    int node = gw / wpn;
    if (node >= ntot) return;
    int fb = (gw % wpn)*128 + lane*4;
    if (fb >= f) return;
    int r0 = g_ROW[node];
    int cnt = g_CNT[node];
    int eend = r0 + cnt;
    float ax0 = 0.f, ay0 = 0.f, az0 = 0.f, aw0 = 0.f;
    float ax1 = 0.f, ay1 = 0.f, az1 = 0.f, aw1 = 0.f;
    int e = r0;
    for (; e + 1 < eend; e += 2){
        int s0 = g_CSRC[e],   s1 = g_CSRC[e+1];
        float w0 = g_CW[e],   w1 = g_CW[e+1];
        float4 v0 = *(const float4*)&X[(size_t)s0*f + fb];
        float4 v1 = *(const float4*)&X[(size_t)s1*f + fb];
        ax0 += w0*v0.x; ay0 += w0*v0.y; az0 += w0*v0.z; aw0 += w0*v0.w;
        ax1 += w1*v1.x; ay1 += w1*v1.y; az1 += w1*v1.z; aw1 += w1*v1.w;
    }
    if (e < eend){
        int s0 = g_CSRC[e];
        float w0 = g_CW[e];
        float4 v0 = *(const float4*)&X[(size_t)s0*f + fb];
        ax0 += w0*v0.x; ay0 += w0*v0.y; az0 += w0*v0.z; aw0 += w0*v0.w;
    }
    float di = g_DINV[node];
    float c = di*di;
    float4 sv = *(const float4*)&X[(size_t)node*f + fb];
    float4 o = { ax0 + ax1 + c*sv.x, ay0 + ay1 + c*sv.y,
                 az0 + az1 + c*sv.z, aw0 + aw1 + c*sv.w };
    *(float4*)&g_S[(size_t)node*f + fb] = o;
}

// ---------------- tf32-split GEMM + fused bias + fused GraphNorm partial stats ---
#define AS_STRIDE 36
#define BS_STRIDE 136
#define SM_AH 0
#define SM_AL (128*AS_STRIDE)
#define SM_BH (2*128*AS_STRIDE)
#define SM_BL (2*128*AS_STRIDE + 32*BS_STRIDE)
#define SM_TOT ((2*128*AS_STRIDE + 2*32*BS_STRIDE)*4)

__device__ __forceinline__ float f2hi(float v){
    float h;
    asm("cvt.rna.tf32.f32 %0, %1;" : "=f"(h) : "f"(v));
    return h;
}
__device__ __forceinline__ void mma8(float* d, uint32_t a0, uint32_t a1, uint32_t a2, uint32_t a3,
                                     uint32_t b0, uint32_t b1){
    asm volatile("mma.sync.aligned.m16n8k8.row.col.f32.tf32.tf32.f32 "
        "{%0,%1,%2,%3}, {%4,%5,%6,%7}, {%8,%9}, {%0,%1,%2,%3};"
        : "+f"(d[0]), "+f"(d[1]), "+f"(d[2]), "+f"(d[3])
        : "r"(a0), "r"(a1), "r"(a2), "r"(a3), "r"(b0), "r"(b1));
}

__global__ void __launch_bounds__(256) k_gemm_tc(const float* __restrict__ A,
                                                 const float* __restrict__ W,
                                                 const float* __restrict__ bias,
                                                 float* __restrict__ C,
                                                 int M, int N, int K, int npg){
    extern __shared__ float sm[];
    float* Ah = sm + SM_AH;
    float* Al = sm + SM_AL;
    float* Bh = sm + SM_BH;
    float* Bl = sm + SM_BL;
    const int tid = threadIdx.x, lane = tid & 31, wid = tid >> 5;
    const int wm = (wid >> 1)*32, wn = (wid & 1)*64;
    const int bm = blockIdx.y*128, bn = blockIdx.x*128;
    const int g4 = lane >> 2, t4 = lane & 3;

    float acc[2][8][4] = {};

    const int K8 = ((K + 7)/8)*8;
    const int nch = (K8 + 31)/32;
    for (int kc = 0; kc < nch; kc++){
        const int k0 = kc*32;
        const int kend = min(32, K8 - k0);
        #pragma unroll
        for (int it = 0; it < 16; it++){
            int idx = it*256 + tid;
            int col = idx & 31, row = idx >> 5;
            int kg = k0 + col;
            float v = (kg < K) ? A[(size_t)(bm+row)*K + kg] : 0.f;
            float h = f2hi(v);
            Ah[row*AS_STRIDE + col] = h;
            Al[row*AS_STRIDE + col] = v - h;
        }
        #pragma unroll
        for (int it = 0; it < 16; it++){
            int idx = it*256 + tid;
            int nc = idx & 127, kr = idx >> 7;
            int kg = k0 + kr;
            float v = (kg < K) ? W[(size_t)kg*N + bn + nc] : 0.f;
            float h = f2hi(v);
            Bh[kr*BS_STRIDE + nc] = h;
            Bl[kr*BS_STRIDE + nc] = v - h;
        }
        __syncthreads();

        for (int kk = 0; kk < kend; kk += 8){
            uint32_t ah[2][4], al[2][4];
            #pragma unroll
            for (int ma = 0; ma < 2; ma++){
                int r0 = (wm + ma*16 + g4)*AS_STRIDE;
                int c0 = kk + t4;
                ah[ma][0] = __float_as_uint(Ah[r0 + c0]);
                ah[ma][1] = __float_as_uint(Ah[r0 + 8*AS_STRIDE + c0]);
                ah[ma][2] = __float_as_uint(Ah[r0 + c0 + 4]);
                ah[ma][3] = __float_as_uint(Ah[r0 + 8*AS_STRIDE + c0 + 4]);
                al[ma][0] = __float_as_uint(Al[r0 + c0]);
                al[ma][1] = __float_as_uint(Al[r0 + 8*AS_STRIDE + c0]);
                al[ma][2] = __float_as_uint(Al[r0 + c0 + 4]);
                al[ma][3] = __float_as_uint(Al[r0 + 8*AS_STRIDE + c0 + 4]);
            }
            #pragma unroll
            for (int jn = 0; jn < 8; jn++){
                int col = wn + jn*8 + g4;
                uint32_t bh0 = __float_as_uint(Bh[(kk + t4)*BS_STRIDE + col]);
                uint32_t bh1 = __float_as_uint(Bh[(kk + 4 + t4)*BS_STRIDE + col]);
                uint32_t bl0 = __float_as_uint(Bl[(kk + t4)*BS_STRIDE + col]);
                uint32_t bl1 = __float_as_uint(Bl[(kk + 4 + t4)*BS_STRIDE + col]);
                #pragma unroll
                for (int ma = 0; ma < 2; ma++){
                    mma8(acc[ma][jn], ah[ma][0], ah[ma][1], ah[ma][2], ah[ma][3], bh0, bh1);
                    mma8(acc[ma][jn], al[ma][0], al[ma][1], al[ma][2], al[ma][3], bh0, bh1);
                    mma8(acc[ma][jn], ah[ma][0], ah[ma][1], ah[ma][2], ah[ma][3], bl0, bl1);
                }
            }
        }
        __syncthreads();
    }

    float ps[16], ps2[16];
    #pragma unroll
    for (int i = 0; i < 16; i++){ ps[i] = 0.f; ps2[i] = 0.f; }

    #pragma unroll
    for (int ma = 0; ma < 2; ma++){
        #pragma unroll
        for (int jn = 0; jn < 8; jn++){
            size_t row0 = (size_t)bm + wm + ma*16 + g4;
            int    colb = bn + wn + jn*8 + t4*2;
            float2 bv = *(const float2*)&bias[colb];
            float a0 = acc[ma][jn][0] + bv.x, a1 = acc[ma][jn][1] + bv.y;
            float a2 = acc[ma][jn][2] + bv.x, a3 = acc[ma][jn][3] + bv.y;
            float2 lo = { a0, a1 };
            float2 hi = { a2, a3 };
            *(float2*)&C[row0*N + colb]     = lo;
            *(float2*)&C[(row0+8)*N + colb] = hi;
            ps [jn*2+0] += a0 + a2;
            ps [jn*2+1] += a1 + a3;
            ps2[jn*2+0] += a0*a0 + a2*a2;
            ps2[jn*2+1] += a1*a1 + a3*a3;
        }
    }
    #pragma unroll
    for (int o = 4; o < 32; o <<= 1){
        #pragma unroll
        for (int i = 0; i < 16; i++){
            ps [i] += __shfl_xor_sync(0xFFFFFFFF, ps [i], o);
            ps2[i] += __shfl_xor_sync(0xFFFFFFFF, ps2[i], o);
        }
    }
    if (lane < 4){
        int g = bm / npg;
        #pragma unroll
        for (int i = 0; i < 16; i++){
            int colg = bn + wn + (i >> 1)*8 + t4*2 + (i & 1);
            atomicAdd(&g_SP1[g*256 + colg], ps[i]);
            atomicAdd(&g_SP2[g*256 + colg], ps2[i]);
        }
    }
}

// ---------------- finalize stats (+ pw norm), self-zero partials ----------------
__global__ void k_finstats(const float* __restrict__ ga, const float* __restrict__ pw,
                           int n, int f){
    int i = blockIdx.x*blockDim.x + threadIdx.x;
    if (i < NG*256){
        int fi = i & 255;
        if (fi < f){
            float s = g_SP1[i], s2 = g_SP2[i];
            g_SP1[i] = 0.f; g_SP2[i] = 0.f;
            float inv_n = 1.f/(float)n;
            float mu = s*inv_n;
            float m2 = s2*inv_n;
            float a = ga[fi];
            float var = m2 - mu*mu*a*(2.f - a);
            g_MU[i] = mu;
            g_RS[i] = rsqrtf(fmaxf(var, 0.f) + EPSN);
        }
    }
    if (blockIdx.x == 0){
        __shared__ float sh[256];
        float v = (threadIdx.x < f) ? pw[threadIdx.x] : 0.f;
        sh[threadIdx.x] = v*v;
        __syncthreads();
        for (int st = 128; st > 0; st >>= 1){
            if (threadIdx.x < st) sh[threadIdx.x] += sh[threadIdx.x + st];
            __syncthreads();
        }
        if (threadIdx.x == 0) g_IPN = rsqrtf(sh[0]);
    }
}

// ---------------- score: norm+relu on the fly, warp per node ----------------
__global__ void k_score(const float* __restrict__ gw, const float* __restrict__ gb,
                        const float* __restrict__ ga, const float* __restrict__ pw,
                        int ntot, int n, int f){
    int node = (blockIdx.x*blockDim.x + threadIdx.x) >> 5;
    int lane = threadIdx.x & 31;
    if (node >= ntot) return;
    int g = node / n;
    float dot = 0.f;
    for (int fc = lane*4; fc < f; fc += 128){
        float4 v  = *(const float4*)&g_AGG[(size_t)node*f + fc];
        float4 mu = *(const float4*)&g_MU[g*256 + fc];
        float4 rs = *(const float4*)&g_RS[g*256 + fc];
        float4 w  = *(const float4*)&gw[fc];
        float4 b  = *(const float4*)&gb[fc];
        float4 a  = *(const float4*)&ga[fc];
        float4 p  = *(const float4*)&pw[fc];
        float x0 = fmaxf(w.x*(v.x - a.x*mu.x)*rs.x + b.x, 0.f);
        float x1 = fmaxf(w.y*(v.y - a.y*mu.y)*rs.y + b.y, 0.f);
        float x2 = fmaxf(w.z*(v.z - a.z*mu.z)*rs.z + b.z, 0.f);
        float x3 = fmaxf(w.w*(v.w - a.w*mu.w)*rs.w + b.w, 0.f);
        dot += x0*p.x + x1*p.y + x2*p.z + x3*p.w;
    }
    #pragma unroll
    for (int o = 16; o > 0; o >>= 1) dot += __shfl_xor_sync(0xFFFFFFFF, dot, o);
    if (lane == 0) g_SCORE[node] = tanhf(dot*g_IPN);
}

// ---------------- per-graph exact top-k (ballot/popc compaction) ----------------
__global__ void k_topk(int n, int k, int nxt){
    __shared__ unsigned keys[4096];
    __shared__ int hist[256];
    __shared__ unsigned sh_prefix;
    __shared__ int sh_rem;
    __shared__ int wgs[16], wes[16];
    __shared__ int tot_g, tot_e;
    __shared__ int base_g, base_e;

    int g = blockIdx.x;
    int tid = threadIdx.x;
    int wid = tid >> 5, lane = tid & 31;
    unsigned lmask = (1u << lane) - 1u;
    if (g == 0 && tid == 0) g_ECNT[nxt] = 0;
    const float* sc = g_SCORE + (size_t)g*n;

    for (int i = tid; i < n; i += blockDim.x){
        unsigned u = __float_as_uint(sc[i]);
        u = (u & 0x80000000u) ? ~u : (u | 0x80000000u);
        keys[i] = u;
    }
    if (tid == 0){ sh_prefix = 0u; sh_rem = k; }
    __syncthreads();

    for (int shift = 24; shift >= 0; shift -= 8){
        for (int i = tid; i < 256; i += blockDim.x) hist[i] = 0;
        __syncthreads();
        unsigned pmask = (shift == 24) ? 0u : (0xFFFFFFFFu << (shift + 8));
        unsigned pref = sh_prefix;
        for (int i = tid; i < n; i += blockDim.x){
            unsigned u = keys[i];
            if ((u & pmask) == pref) atomicAdd(&hist[(u >> shift) & 0xFF], 1);
        }
        __syncthreads();
        if (tid == 0){
            int rem = sh_rem, b;
            for (b = 255; b >= 0; b--){
                if (rem <= hist[b]) break;
                rem -= hist[b];
            }
            sh_prefix |= ((unsigned)b) << shift;
            sh_rem = rem;
        }
        __syncthreads();
    }
    unsigned thr = sh_prefix;
    int need = sh_rem;
    if (tid == 0){ base_g = 0; base_e = 0; }
    __syncthreads();

    for (int c0 = 0; c0 < n; c0 += blockDim.x){
        int i = c0 + tid;
        int gf = 0, ef = 0;
        if (i < n){
            unsigned u = keys[i];
            gf = (u > thr);
            ef = (u == thr);
        }
        unsigned bg = __ballot_sync(0xFFFFFFFF, gf);
        unsigned be = __ballot_sync(0xFFFFFFFF, ef);
        int pg = __popc(bg & lmask);
        int pe = __popc(be & lmask);
        if (lane == 0){ wgs[wid] = __popc(bg); wes[wid] = __popc(be); }
        __syncthreads();
        if (tid < 16){
            int vg = wgs[tid], ve = wes[tid];
            int ig = vg, ie = ve;
            #pragma unroll
            for (int o = 1; o < 16; o <<= 1){
                int t = __shfl_up_sync(0xFFFFu, ig, o); if (lane >= o) ig += t;
                t = __shfl_up_sync(0xFFFFu, ie, o);     if (lane >= o) ie += t;
            }
            wgs[tid] = ig - vg;   // exclusive prefix
            wes[tid] = ie - ve;
            if (tid == 15){ tot_g = ig; tot_e = ie; }
        }
        __syncthreads();
        if (i < n){
            int g_before = base_g + wgs[wid] + pg;
            int e_before = base_e + wes[wid] + pe;
            bool kept = gf || (ef && (e_before < need));
            int oldg = g*n + i;
            if (kept){
                int newlocal = g_before + min(e_before, need);
                int newglobal = g*k + newlocal;
                g_MAP[oldg]        = newglobal;
                g_PERMG[newglobal] = oldg;
                g_GATE[newglobal]  = sc[i];
            } else {
                g_MAP[oldg] = -1;
            }
        }
        __syncthreads();
        if (tid == 0){ base_g += tot_g; base_e += tot_e; }
        __syncthreads();
    }
}

// ---------------- gather kept nodes with fused norm+relu+gate (layers 1,2) ------
__global__ void k_gather_norm(const float* __restrict__ gw, const float* __restrict__ gb,
                              const float* __restrict__ ga,
                              int tot_new, int n, int f){
    int per = f >> 2;
    size_t idx = (size_t)blockIdx.x*blockDim.x + threadIdx.x;
    if (idx >= (size_t)tot_new*per) return;
    int j  = (int)(idx / per);
    int fc = (int)(idx % per)*4;
    int old = g_PERMG[j];
    int g = old / n;
    float gv = g_GATE[j];
    float4 v  = *(const float4*)&g_AGG[(size_t)old*f + fc];
    float4 mu = *(const float4*)&g_MU[g*256 + fc];
    float4 rs = *(const float4*)&g_RS[g*256 + fc];
    float4 w  = *(const float4*)&gw[fc];
    float4 b  = *(const float4*)&gb[fc];
    float4 a  = *(const float4*)&ga[fc];
    float4 o;
    o.x = fmaxf(w.x*(v.x - a.x*mu.x)*rs.x + b.x, 0.f)*gv;
    o.y = fmaxf(w.y*(v.y - a.y*mu.y)*rs.y + b.y, 0.f)*gv;
    o.z = fmaxf(w.z*(v.z - a.z*mu.z)*rs.z + b.z, 0.f)*gv;
    o.w = fmaxf(w.w*(v.w - a.w*mu.w)*rs.w + b.w, 0.f)*gv;
    *(float4*)&g_X[(size_t)j*f + fc] = o;
}

// ---------------- remap + compact edges + count next in-degrees ----------------
__global__ void k_remap(int cur){
    int e = blockIdx.x*blockDim.x + threadIdx.x;
    if (e >= g_ECNT[cur]) return;
    int s = g_MAP[g_ESRC[cur][e]];
    int d = g_MAP[g_EDST[cur][e]];
    if (s >= 0 && d >= 0){
        int p = atomicAdd(&g_ECNT[cur^1], 1);
        g_ESRC[cur^1][p] = s;
        g_EDST[cur^1][p] = d;
        atomicAdd(&g_CNT[d], 1);
    }
}

// ---------------- fused L3 gather + readout ----------------
__global__ void k_readout(const float* __restrict__ gw, const float* __restrict__ gb,
                          const float* __restrict__ ga, int n){
    int gg = blockIdx.x;
    int f  = threadIdx.x;   // 256
    float w = gw[f], b = gb[f], a = ga[f];
    float mu = g_MU[gg*256 + f], rs = g_RS[gg*256 + f];
    float s = 0.f, mx = -INFINITY;
    for (int i = 0; i < 512; i++){
        int j = gg*512 + i;
        int old = g_PERMG[j];
        float gv = g_GATE[j];
        float v = g_AGG[(size_t)old*256 + f];
        float x = fmaxf(w*(v - a*mu)*rs + b, 0.f)*gv;
        s += x;
        mx = fmaxf(mx, x);
    }
    g_PMEAN[gg*256 + f] = s*(1.f/512.f);
    g_PMAX [gg*256 + f] = mx;
}

__global__ void k_final(float* __restrict__ out){
    int idx = blockIdx.x*blockDim.x + threadIdx.x;
    if (idx >= BATCH*512) return;
    int b = idx / 512, c = idx % 512;
    float acc = 0.f;
    if (c < 256){
        for (int t = 0; t < TS; t++) acc += g_PMEAN[(t*BATCH + b)*256 + c];
    } else {
        for (int t = 0; t < TS; t++) acc += g_PMAX[(t*BATCH + b)*256 + (c-256)];
    }
    out[idx] = acc*(1.f/(float)TS);
}

// ---------------- host orchestration ----------------
extern "C" void kernel_launch(void* const* d_in, const int* in_sizes, int n_in,
                              void* d_out, int out_size){
    const float* x_seq = (const float*)d_in[0];
    const int*   ei    = (const int*)  d_in[1];
    const float* W [3] = {(const float*)d_in[2],  (const float*)d_in[4],  (const float*)d_in[6]};
    const float* bb[3] = {(const float*)d_in[3],  (const float*)d_in[5],  (const float*)d_in[7]};
    const float* gw[3] = {(const float*)d_in[8],  (const float*)d_in[11], (const float*)d_in[14]};
    const float* gb[3] = {(const float*)d_in[9],  (const float*)d_in[12], (const float*)d_in[15]};
    const float* ga[3] = {(const float*)d_in[10], (const float*)d_in[13], (const float*)d_in[16]};
    const float* pw[3] = {(const float*)d_in[17], (const float*)d_in[18], (const float*)d_in[19]};
    float* out = (float*)d_out;

    float *pS, *pX, *pAGG;
    int *pCNT, *pCUR;
    cudaGetSymbolAddress((void**)&pS,   g_S);
    cudaGetSymbolAddress((void**)&pX,   g_X);
    cudaGetSymbolAddress((void**)&pAGG, g_AGG);
    cudaGetSymbolAddress((void**)&pCNT, g_CNT);
    cudaGetSymbolAddress((void**)&pCUR, g_CUR);

    cudaFuncSetAttribute(k_gemm_tc, cudaFuncAttributeMaxDynamicSharedMemorySize, SM_TOT);

    const int nin [3] = {4096, 2048, 1024};
    const int nk  [3] = {2048, 1024, 512};
    const int fin [3] = {100, 128, 128};
    const int fout[3] = {128, 128, 256};

    k_zero2i<<<(NG*NPG + 255)/256, 256>>>(pCNT, pCUR, NG*NPG);
    k_zeroSP<<<(NG*256 + 255)/256, 256>>>();
    k_edge_init<<<NEDGE/256, 256>>>(ei);

    const float* A = x_seq;
    for (int l = 0; l < 3; l++){
        int n = nin[l], k = nk[l], fi = fin[l], fo = fout[l];
        int ntot = NG * n;
        int cur = l & 1, nxt = cur ^ 1;
        int nb = ntot / 512;
        int wpn = (fi + 127)/128;

        k_scan1 <<<nb, 512>>>(ntot);
        k_scan3d<<<nb, 512>>>(ntot);
        k_fill  <<<NEDGE/256, 256>>>(cur);

        k_aggregate<<<ntot*wpn/8, 256>>>(A, ntot, fi, wpn);
        k_gemm_tc<<<dim3(fo/128, ntot/128), 256, SM_TOT>>>(pS, W[l], bb[l], pAGG, ntot, fo, fi, n);

        k_finstats<<<(NG*256 + 255)/256, 256>>>(ga[l], pw[l], n, fo);
        k_score<<<ntot/8, 256>>>(gw[l], gb[l], ga[l], pw[l], ntot, n, fo);

        k_topk<<<NG, 512>>>(n, k, nxt);
        int tot_new = NG * k;
        if (l < 2){
            k_zero2i<<<(tot_new + 255)/256, 256>>>(pCNT, pCUR, tot_new);
            k_remap<<<NEDGE/256, 256>>>(cur);
            k_gather_norm<<<(int)(((size_t)tot_new*(fo/4) + 255)/256), 256>>>(gw[l], gb[l], ga[l], tot_new, n, fo);
            A = pX;
        }
    }

    k_readout<<<NG, 256>>>(gw[2], gb[2], ga[2], nin[2]);
    k_final<<<(BATCH*512 + 255)/256, 256>>>(out);
}

// round 13
// speedup vs baseline: 1.3220x; 1.0142x over previous
#include <cuda_runtime.h>
#include <math.h>
#include <stdint.h>

// ---------------- problem constants ----------------
#define TS     8
#define BATCH  16
#define NPG    4096
#define NEDGE  (TS*BATCH*32768)   // 4,194,304 edges (all timesteps, layer 1)
#define NG     (TS*BATCH)         // 128 graphs
#define EPSN   1e-5f
#define MAXN   524288

// ---------------- static device scratch ----------------
__device__ float g_S  [67108864];   // aggregated input  S = A_norm * X
__device__ float g_AGG[67108864];   // gcn output Y = S*W + b
__device__ float g_X  [33554432];   // compacted layer input (normalized+gated)
__device__ float g_DINV[MAXN];
__device__ float g_SCORE[MAXN];
__device__ int   g_MAP [MAXN];
__device__ int   g_PERMG[262144];
__device__ float g_GATE [262144];
__device__ int   g_CNT[MAXN];
__device__ int   g_CUR[MAXN];
__device__ int   g_ROW[MAXN];
__device__ int   g_BSUM[1024];
__device__ int   g_CSRC[NEDGE];
__device__ float g_CW [NEDGE];
__device__ int   g_ESRC[2][NEDGE];
__device__ int   g_EDST[2][NEDGE];
__device__ int   g_ECNT[2];
__device__ float g_SP1[NG*256];     // invariant: zero between uses (finstats self-zeroes)
__device__ float g_SP2[NG*256];
__device__ float g_MU [NG*256];
__device__ float g_RS [NG*256];
__device__ float g_IPN;
__device__ float g_PMEAN[NG*256];
__device__ float g_PMAX [NG*256];

// ---------------- utility ----------------
__global__ void k_zero2i(int* a, int* b, int cnt){
    int i = blockIdx.x*blockDim.x + threadIdx.x;
    if (i < cnt){ a[i] = 0; b[i] = 0; }
}

__global__ void k_edge_init(const int* __restrict__ ei){
    int idx = blockIdx.x*blockDim.x + threadIdx.x;
    if (idx == 0){ g_ECNT[0] = NEDGE; g_ECNT[1] = 0; }
    if (idx >= NEDGE) return;
    const int E = 32768*BATCH;
    int t = idx / E, e = idx % E;
    int base = t * (BATCH*NPG);
    int s = ei[(size_t)t*2*E + e]     + base;
    int d = ei[(size_t)t*2*E + E + e] + base;
    g_ESRC[0][idx] = s;
    g_EDST[0][idx] = d;
    atomicAdd(&g_CNT[d], 1);
}

// ---------------- CSR build ----------------
__global__ void k_scan1(int n){
    __shared__ int sh[512];
    int i = blockIdx.x*512 + threadIdx.x;
    int v = (i < n) ? g_CNT[i] : 0;
    sh[threadIdx.x] = v;
    __syncthreads();
    for (int st = 1; st < 512; st <<= 1){
        int t = (threadIdx.x >= st) ? sh[threadIdx.x - st] : 0;
        __syncthreads();
        sh[threadIdx.x] += t;
        __syncthreads();
    }
    if (i < n) g_ROW[i] = sh[threadIdx.x] - v;
    if (threadIdx.x == 511) g_BSUM[blockIdx.x] = sh[511];
}
__global__ void k_scan3d(int n){
    __shared__ int sh[512];
    int bid = blockIdx.x, tid = threadIdx.x;
    int acc = 0;
    for (int j = tid; j < bid; j += 512) acc += g_BSUM[j];
    sh[tid] = acc;
    __syncthreads();
    for (int st = 256; st > 0; st >>= 1){
        if (tid < st) sh[tid] += sh[tid + st];
        __syncthreads();
    }
    int base = sh[0];
    int i = bid*512 + tid;
    if (i < n){
        g_ROW[i] += base;
        g_DINV[i] = rsqrtf(1.f + (float)g_CNT[i]);
    }
}

__global__ void k_fill(int cur){
    int e = blockIdx.x*blockDim.x + threadIdx.x;
    if (e >= g_ECNT[cur]) return;
    int s = g_ESRC[cur][e], d = g_EDST[cur][e];
    int slot = g_ROW[d] + atomicAdd(&g_CUR[d], 1);
    g_CSRC[slot] = s;
    g_CW[slot]   = g_DINV[s]*g_DINV[d];
}

// ---------------- aggregate-first: S[d] = sum w_e X[s] + dinv[d]^2 X[d] ----------
__global__ void k_aggregate(const float* __restrict__ X, int ntot, int f, int wpn){
    int gw = (blockIdx.x*blockDim.x + threadIdx.x) >> 5;
    int lane = threadIdx.x & 31;
    int node = gw / wpn;
    if (node >= ntot) return;
    int fb = (gw % wpn)*128 + lane*4;
    if (fb >= f) return;
    int r0 = g_ROW[node];
    int cnt = g_CNT[node];
    int eend = r0 + cnt;
    float ax0 = 0.f, ay0 = 0.f, az0 = 0.f, aw0 = 0.f;
    float ax1 = 0.f, ay1 = 0.f, az1 = 0.f, aw1 = 0.f;
    int e = r0;
    for (; e + 1 < eend; e += 2){
        int s0 = g_CSRC[e],   s1 = g_CSRC[e+1];
        float w0 = g_CW[e],   w1 = g_CW[e+1];
        float4 v0 = *(const float4*)&X[(size_t)s0*f + fb];
        float4 v1 = *(const float4*)&X[(size_t)s1*f + fb];
        ax0 += w0*v0.x; ay0 += w0*v0.y; az0 += w0*v0.z; aw0 += w0*v0.w;
        ax1 += w1*v1.x; ay1 += w1*v1.y; az1 += w1*v1.z; aw1 += w1*v1.w;
    }
    if (e < eend){
        int s0 = g_CSRC[e];
        float w0 = g_CW[e];
        float4 v0 = *(const float4*)&X[(size_t)s0*f + fb];
        ax0 += w0*v0.x; ay0 += w0*v0.y; az0 += w0*v0.z; aw0 += w0*v0.w;
    }
    float di = g_DINV[node];
    float c = di*di;
    float4 sv = *(const float4*)&X[(size_t)node*f + fb];
    float4 o = { ax0 + ax1 + c*sv.x, ay0 + ay1 + c*sv.y,
                 az0 + az1 + c*sv.z, aw0 + aw1 + c*sv.w };
    *(float4*)&g_S[(size_t)node*f + fb] = o;
}

// ---------------- tf32-split GEMM + fused bias + fused GraphNorm partial stats ---
#define AS_STRIDE 36
#define BS_STRIDE 136
#define SM_AH 0
#define SM_AL (128*AS_STRIDE)
#define SM_BH (2*128*AS_STRIDE)
#define SM_BL (2*128*AS_STRIDE + 32*BS_STRIDE)
#define SM_TOT ((2*128*AS_STRIDE + 2*32*BS_STRIDE)*4)

__device__ __forceinline__ float f2hi(float v){
    float h;
    asm("cvt.rna.tf32.f32 %0, %1;" : "=f"(h) : "f"(v));
    return h;
}
__device__ __forceinline__ void mma8(float* d, uint32_t a0, uint32_t a1, uint32_t a2, uint32_t a3,
                                     uint32_t b0, uint32_t b1){
    asm volatile("mma.sync.aligned.m16n8k8.row.col.f32.tf32.tf32.f32 "
        "{%0,%1,%2,%3}, {%4,%5,%6,%7}, {%8,%9}, {%0,%1,%2,%3};"
        : "+f"(d[0]), "+f"(d[1]), "+f"(d[2]), "+f"(d[3])
        : "r"(a0), "r"(a1), "r"(a2), "r"(a3), "r"(b0), "r"(b1));
}

__global__ void __launch_bounds__(256) k_gemm_tc(const float* __restrict__ A,
                                                 const float* __restrict__ W,
                                                 const float* __restrict__ bias,
                                                 float* __restrict__ C,
                                                 int M, int N, int K, int npg){
    extern __shared__ float sm[];
    float* Ah = sm + SM_AH;
    float* Al = sm + SM_AL;
    float* Bh = sm + SM_BH;
    float* Bl = sm + SM_BL;
    const int tid = threadIdx.x, lane = tid & 31, wid = tid >> 5;
    const int wm = (wid >> 1)*32, wn = (wid & 1)*64;
    const int bm = blockIdx.y*128, bn = blockIdx.x*128;
    const int g4 = lane >> 2, t4 = lane & 3;

    float acc[2][8][4] = {};

    const int K8 = ((K + 7)/8)*8;
    const int nch = (K8 + 31)/32;
    for (int kc = 0; kc < nch; kc++){
        const int k0 = kc*32;
        const int kend = min(32, K8 - k0);
        #pragma unroll
        for (int it = 0; it < 16; it++){
            int idx = it*256 + tid;
            int col = idx & 31, row = idx >> 5;
            int kg = k0 + col;
            float v = (kg < K) ? A[(size_t)(bm+row)*K + kg] : 0.f;
            float h = f2hi(v);
            Ah[row*AS_STRIDE + col] = h;
            Al[row*AS_STRIDE + col] = v - h;
        }
        #pragma unroll
        for (int it = 0; it < 16; it++){
            int idx = it*256 + tid;
            int nc = idx & 127, kr = idx >> 7;
            int kg = k0 + kr;
            float v = (kg < K) ? W[(size_t)kg*N + bn + nc] : 0.f;
            float h = f2hi(v);
            Bh[kr*BS_STRIDE + nc] = h;
            Bl[kr*BS_STRIDE + nc] = v - h;
        }
        __syncthreads();

        for (int kk = 0; kk < kend; kk += 8){
            uint32_t ah[2][4], al[2][4];
            #pragma unroll
            for (int ma = 0; ma < 2; ma++){
                int r0 = (wm + ma*16 + g4)*AS_STRIDE;
                int c0 = kk + t4;
                ah[ma][0] = __float_as_uint(Ah[r0 + c0]);
                ah[ma][1] = __float_as_uint(Ah[r0 + 8*AS_STRIDE + c0]);
                ah[ma][2] = __float_as_uint(Ah[r0 + c0 + 4]);
                ah[ma][3] = __float_as_uint(Ah[r0 + 8*AS_STRIDE + c0 + 4]);
                al[ma][0] = __float_as_uint(Al[r0 + c0]);
                al[ma][1] = __float_as_uint(Al[r0 + 8*AS_STRIDE + c0]);
                al[ma][2] = __float_as_uint(Al[r0 + c0 + 4]);
                al[ma][3] = __float_as_uint(Al[r0 + 8*AS_STRIDE + c0 + 4]);
            }
            #pragma unroll
            for (int jn = 0; jn < 8; jn++){
                int col = wn + jn*8 + g4;
                uint32_t bh0 = __float_as_uint(Bh[(kk + t4)*BS_STRIDE + col]);
                uint32_t bh1 = __float_as_uint(Bh[(kk + 4 + t4)*BS_STRIDE + col]);
                uint32_t bl0 = __float_as_uint(Bl[(kk + t4)*BS_STRIDE + col]);
                uint32_t bl1 = __float_as_uint(Bl[(kk + 4 + t4)*BS_STRIDE + col]);
                #pragma unroll
                for (int ma = 0; ma < 2; ma++){
                    mma8(acc[ma][jn], ah[ma][0], ah[ma][1], ah[ma][2], ah[ma][3], bh0, bh1);
                    mma8(acc[ma][jn], al[ma][0], al[ma][1], al[ma][2], al[ma][3], bh0, bh1);
                    mma8(acc[ma][jn], ah[ma][0], ah[ma][1], ah[ma][2], ah[ma][3], bl0, bl1);
                }
            }
        }
        __syncthreads();
    }

    float ps[16], ps2[16];
    #pragma unroll
    for (int i = 0; i < 16; i++){ ps[i] = 0.f; ps2[i] = 0.f; }

    #pragma unroll
    for (int ma = 0; ma < 2; ma++){
        #pragma unroll
        for (int jn = 0; jn < 8; jn++){
            size_t row0 = (size_t)bm + wm + ma*16 + g4;
            int    colb = bn + wn + jn*8 + t4*2;
            float2 bv = *(const float2*)&bias[colb];
            float a0 = acc[ma][jn][0] + bv.x, a1 = acc[ma][jn][1] + bv.y;
            float a2 = acc[ma][jn][2] + bv.x, a3 = acc[ma][jn][3] + bv.y;
            float2 lo = { a0, a1 };
            float2 hi = { a2, a3 };
            *(float2*)&C[row0*N + colb]     = lo;
            *(float2*)&C[(row0+8)*N + colb] = hi;
            ps [jn*2+0] += a0 + a2;
            ps [jn*2+1] += a1 + a3;
            ps2[jn*2+0] += a0*a0 + a2*a2;
            ps2[jn*2+1] += a1*a1 + a3*a3;
        }
    }
    #pragma unroll
    for (int o = 4; o < 32; o <<= 1){
        #pragma unroll
        for (int i = 0; i < 16; i++){
            ps [i] += __shfl_xor_sync(0xFFFFFFFF, ps [i], o);
            ps2[i] += __shfl_xor_sync(0xFFFFFFFF, ps2[i], o);
        }
    }
    if (lane < 4){
        int g = bm / npg;
        #pragma unroll
        for (int i = 0; i < 16; i++){
            int colg = bn + wn + (i >> 1)*8 + t4*2 + (i & 1);
            atomicAdd(&g_SP1[g*256 + colg], ps[i]);
            atomicAdd(&g_SP2[g*256 + colg], ps2[i]);
        }
    }
}

// ---------------- finalize stats (+ pw norm), self-zero partials ----------------
__global__ void k_finstats(const float* __restrict__ ga, const float* __restrict__ pw,
                           int n, int f){
    int i = blockIdx.x*blockDim.x + threadIdx.x;
    if (i < NG*256){
        int fi = i & 255;
        if (fi < f){
            float s = g_SP1[i], s2 = g_SP2[i];
            g_SP1[i] = 0.f; g_SP2[i] = 0.f;
            float inv_n = 1.f/(float)n;
            float mu = s*inv_n;
            float m2 = s2*inv_n;
            float a = ga[fi];
            float var = m2 - mu*mu*a*(2.f - a);
            g_MU[i] = mu;
            g_RS[i] = rsqrtf(fmaxf(var, 0.f) + EPSN);
        }
    }
    if (blockIdx.x == 0){
        __shared__ float sh[256];
        float v = (threadIdx.x < f) ? pw[threadIdx.x] : 0.f;
        sh[threadIdx.x] = v*v;
        __syncthreads();
        for (int st = 128; st > 0; st >>= 1){
            if (threadIdx.x < st) sh[threadIdx.x] += sh[threadIdx.x + st];
            __syncthreads();
        }
        if (threadIdx.x == 0) g_IPN = rsqrtf(sh[0]);
    }
}

// ---------------- score: norm+relu on the fly, warp per node ----------------
__global__ void k_score(const float* __restrict__ gw, const float* __restrict__ gb,
                        const float* __restrict__ ga, const float* __restrict__ pw,
                        int ntot, int n, int f){
    int node = (blockIdx.x*blockDim.x + threadIdx.x) >> 5;
    int lane = threadIdx.x & 31;
    if (node >= ntot) return;
    int g = node / n;
    float dot = 0.f;
    for (int fc = lane*4; fc < f; fc += 128){
        float4 v  = *(const float4*)&g_AGG[(size_t)node*f + fc];
        float4 mu = *(const float4*)&g_MU[g*256 + fc];
        float4 rs = *(const float4*)&g_RS[g*256 + fc];
        float4 w  = *(const float4*)&gw[fc];
        float4 b  = *(const float4*)&gb[fc];
        float4 a  = *(const float4*)&ga[fc];
        float4 p  = *(const float4*)&pw[fc];
        float x0 = fmaxf(w.x*(v.x - a.x*mu.x)*rs.x + b.x, 0.f);
        float x1 = fmaxf(w.y*(v.y - a.y*mu.y)*rs.y + b.y, 0.f);
        float x2 = fmaxf(w.z*(v.z - a.z*mu.z)*rs.z + b.z, 0.f);
        float x3 = fmaxf(w.w*(v.w - a.w*mu.w)*rs.w + b.w, 0.f);
        dot += x0*p.x + x1*p.y + x2*p.z + x3*p.w;
    }
    #pragma unroll
    for (int o = 16; o > 0; o >>= 1) dot += __shfl_xor_sync(0xFFFFFFFF, dot, o);
    if (lane == 0) g_SCORE[node] = tanhf(dot*g_IPN);
}

// ---------------- per-graph exact top-k (ballot/popc compaction) ----------------
__global__ void k_topk(int n, int k, int nxt){
    __shared__ unsigned keys[4096];
    __shared__ int hist[256];
    __shared__ unsigned sh_prefix;
    __shared__ int sh_rem;
    __shared__ int wgs[16], wes[16];
    __shared__ int tot_g, tot_e;
    __shared__ int base_g, base_e;

    int g = blockIdx.x;
    int tid = threadIdx.x;
    int wid = tid >> 5, lane = tid & 31;
    unsigned lmask = (1u << lane) - 1u;
    if (g == 0 && tid == 0) g_ECNT[nxt] = 0;
    const float* sc = g_SCORE + (size_t)g*n;

    for (int i = tid; i < n; i += blockDim.x){
        unsigned u = __float_as_uint(sc[i]);
        u = (u & 0x80000000u) ? ~u : (u | 0x80000000u);
        keys[i] = u;
    }
    if (tid == 0){ sh_prefix = 0u; sh_rem = k; }
    __syncthreads();

    for (int shift = 24; shift >= 0; shift -= 8){
        for (int i = tid; i < 256; i += blockDim.x) hist[i] = 0;
        __syncthreads();
        unsigned pmask = (shift == 24) ? 0u : (0xFFFFFFFFu << (shift + 8));
        unsigned pref = sh_prefix;
        for (int i = tid; i < n; i += blockDim.x){
            unsigned u = keys[i];
            if ((u & pmask) == pref) atomicAdd(&hist[(u >> shift) & 0xFF], 1);
        }
        __syncthreads();
        if (tid == 0){
            int rem = sh_rem, b;
            for (b = 255; b >= 0; b--){
                if (rem <= hist[b]) break;
                rem -= hist[b];
            }
            sh_prefix |= ((unsigned)b) << shift;
            sh_rem = rem;
        }
        __syncthreads();
    }
    unsigned thr = sh_prefix;
    int need = sh_rem;
    if (tid == 0){ base_g = 0; base_e = 0; }
    __syncthreads();

    for (int c0 = 0; c0 < n; c0 += blockDim.x){
        int i = c0 + tid;
        int gf = 0, ef = 0;
        if (i < n){
            unsigned u = keys[i];
            gf = (u > thr);
            ef = (u == thr);
        }
        unsigned bg = __ballot_sync(0xFFFFFFFF, gf);
        unsigned be = __ballot_sync(0xFFFFFFFF, ef);
        int pg = __popc(bg & lmask);
        int pe = __popc(be & lmask);
        if (lane == 0){ wgs[wid] = __popc(bg); wes[wid] = __popc(be); }
        __syncthreads();
        if (tid < 16){
            int vg = wgs[tid], ve = wes[tid];
            int ig = vg, ie = ve;
            #pragma unroll
            for (int o = 1; o < 16; o <<= 1){
                int t = __shfl_up_sync(0xFFFFu, ig, o); if (lane >= o) ig += t;
                t = __shfl_up_sync(0xFFFFu, ie, o);     if (lane >= o) ie += t;
            }
            wgs[tid] = ig - vg;
            wes[tid] = ie - ve;
            if (tid == 15){ tot_g = ig; tot_e = ie; }
        }
        __syncthreads();
        if (i < n){
            int g_before = base_g + wgs[wid] + pg;
            int e_before = base_e + wes[wid] + pe;
            bool kept = gf || (ef && (e_before < need));
            int oldg = g*n + i;
            if (kept){
                int newlocal = g_before + min(e_before, need);
                int newglobal = g*k + newlocal;
                g_MAP[oldg]        = newglobal;
                g_PERMG[newglobal] = oldg;
                g_GATE[newglobal]  = sc[i];
            } else {
                g_MAP[oldg] = -1;
            }
        }
        __syncthreads();
        if (tid == 0){ base_g += tot_g; base_e += tot_e; }
        __syncthreads();
    }
}

// ---------------- gather kept nodes with fused norm+relu+gate (layers 1,2) ------
__global__ void k_gather_norm(const float* __restrict__ gw, const float* __restrict__ gb,
                              const float* __restrict__ ga,
                              int tot_new, int n, int f){
    int per = f >> 2;
    size_t idx = (size_t)blockIdx.x*blockDim.x + threadIdx.x;
    if (idx >= (size_t)tot_new*per) return;
    int j  = (int)(idx / per);
    int fc = (int)(idx % per)*4;
    int old = g_PERMG[j];
    int g = old / n;
    float gv = g_GATE[j];
    float4 v  = *(const float4*)&g_AGG[(size_t)old*f + fc];
    float4 mu = *(const float4*)&g_MU[g*256 + fc];
    float4 rs = *(const float4*)&g_RS[g*256 + fc];
    float4 w  = *(const float4*)&gw[fc];
    float4 b  = *(const float4*)&gb[fc];
    float4 a  = *(const float4*)&ga[fc];
    float4 o;
    o.x = fmaxf(w.x*(v.x - a.x*mu.x)*rs.x + b.x, 0.f)*gv;
    o.y = fmaxf(w.y*(v.y - a.y*mu.y)*rs.y + b.y, 0.f)*gv;
    o.z = fmaxf(w.z*(v.z - a.z*mu.z)*rs.z + b.z, 0.f)*gv;
    o.w = fmaxf(w.w*(v.w - a.w*mu.w)*rs.w + b.w, 0.f)*gv;
    *(float4*)&g_X[(size_t)j*f + fc] = o;
}

// ---------------- remap + compact edges + count next in-degrees ----------------
__global__ void k_remap(int cur){
    int e = blockIdx.x*blockDim.x + threadIdx.x;
    if (e >= g_ECNT[cur]) return;
    int s = g_MAP[g_ESRC[cur][e]];
    int d = g_MAP[g_EDST[cur][e]];
    if (s >= 0 && d >= 0){
        int p = atomicAdd(&g_ECNT[cur^1], 1);
        g_ESRC[cur^1][p] = s;
        g_EDST[cur^1][p] = d;
        atomicAdd(&g_CNT[d], 1);
    }
}

// ---------------- fused L3 gather + readout ----------------
__global__ void k_readout(const float* __restrict__ gw, const float* __restrict__ gb,
                          const float* __restrict__ ga, int n){
    int gg = blockIdx.x;
    int f  = threadIdx.x;   // 256
    float w = gw[f], b = gb[f], a = ga[f];
    float mu = g_MU[gg*256 + f], rs = g_RS[gg*256 + f];
    float s = 0.f, mx = -INFINITY;
    for (int i = 0; i < 512; i++){
        int j = gg*512 + i;
        int old = g_PERMG[j];
        float gv = g_GATE[j];
        float v = g_AGG[(size_t)old*256 + f];
        float x = fmaxf(w*(v - a*mu)*rs + b, 0.f)*gv;
        s += x;
        mx = fmaxf(mx, x);
    }
    g_PMEAN[gg*256 + f] = s*(1.f/512.f);
    g_PMAX [gg*256 + f] = mx;
}

__global__ void k_final(float* __restrict__ out){
    int idx = blockIdx.x*blockDim.x + threadIdx.x;
    if (idx >= BATCH*512) return;
    int b = idx / 512, c = idx % 512;
    float acc = 0.f;
    if (c < 256){
        for (int t = 0; t < TS; t++) acc += g_PMEAN[(t*BATCH + b)*256 + c];
    } else {
        for (int t = 0; t < TS; t++) acc += g_PMAX[(t*BATCH + b)*256 + (c-256)];
    }
    out[idx] = acc*(1.f/(float)TS);
}

// ---------------- host orchestration ----------------
extern "C" void kernel_launch(void* const* d_in, const int* in_sizes, int n_in,
                              void* d_out, int out_size){
    const float* x_seq = (const float*)d_in[0];
    const int*   ei    = (const int*)  d_in[1];
    const float* W [3] = {(const float*)d_in[2],  (const float*)d_in[4],  (const float*)d_in[6]};
    const float* bb[3] = {(const float*)d_in[3],  (const float*)d_in[5],  (const float*)d_in[7]};
    const float* gw[3] = {(const float*)d_in[8],  (const float*)d_in[11], (const float*)d_in[14]};
    const float* gb[3] = {(const float*)d_in[9],  (const float*)d_in[12], (const float*)d_in[15]};
    const float* ga[3] = {(const float*)d_in[10], (const float*)d_in[13], (const float*)d_in[16]};
    const float* pw[3] = {(const float*)d_in[17], (const float*)d_in[18], (const float*)d_in[19]};
    float* out = (float*)d_out;

    float *pS, *pX, *pAGG;
    int *pCNT, *pCUR;
    cudaGetSymbolAddress((void**)&pS,   g_S);
    cudaGetSymbolAddress((void**)&pX,   g_X);
    cudaGetSymbolAddress((void**)&pAGG, g_AGG);
    cudaGetSymbolAddress((void**)&pCNT, g_CNT);
    cudaGetSymbolAddress((void**)&pCUR, g_CUR);

    static cudaStream_t s2 = nullptr;
    static cudaEvent_t evF[2], evJ[2];
    if (!s2){
        cudaStreamCreate(&s2);
        for (int i = 0; i < 2; i++){
            cudaEventCreateWithFlags(&evF[i], cudaEventDisableTiming);
            cudaEventCreateWithFlags(&evJ[i], cudaEventDisableTiming);
        }
        cudaFuncSetAttribute(k_gemm_tc, cudaFuncAttributeMaxDynamicSharedMemorySize, SM_TOT);
    }

    const int nin [3] = {4096, 2048, 1024};
    const int nk  [3] = {2048, 1024, 512};
    const int fin [3] = {100, 128, 128};
    const int fout[3] = {128, 128, 256};

    // layer-1 CSR build (SP partials are zero by module-load / finstats invariant)
    k_zero2i<<<(NG*NPG + 255)/256, 256>>>(pCNT, pCUR, NG*NPG);
    k_edge_init<<<NEDGE/256, 256>>>(ei);
    k_scan1 <<<NG*NPG/512, 512>>>(NG*NPG);
    k_scan3d<<<NG*NPG/512, 512>>>(NG*NPG);
    k_fill  <<<NEDGE/256, 256>>>(0);

    const float* A = x_seq;
    for (int l = 0; l < 3; l++){
        int n = nin[l], k = nk[l], fi = fin[l], fo = fout[l];
        int ntot = NG * n;
        int cur = l & 1, nxt = cur ^ 1;
        int wpn = (fi + 127)/128;

        k_aggregate<<<ntot*wpn/8, 256>>>(A, ntot, fi, wpn);
        k_gemm_tc<<<dim3(fo/128, ntot/128), 256, SM_TOT>>>(pS, W[l], bb[l], pAGG, ntot, fo, fi, n);

        k_finstats<<<(NG*256 + 255)/256, 256>>>(ga[l], pw[l], n, fo);
        k_score<<<ntot/8, 256>>>(gw[l], gb[l], ga[l], pw[l], ntot, n, fo);

        k_topk<<<NG, 512>>>(n, k, nxt);

        if (l < 2){
            int tot_new = NG * k;
            int nb2 = tot_new / 512;
            // fork: next-layer CSR build on s2, gather on main stream
            cudaEventRecord(evF[l], 0);
            cudaStreamWaitEvent(s2, evF[l], 0);
            k_zero2i<<<(tot_new + 255)/256, 256, 0, s2>>>(pCNT, pCUR, tot_new);
            k_remap <<<NEDGE/256, 256, 0, s2>>>(cur);
            k_scan1 <<<nb2, 512, 0, s2>>>(tot_new);
            k_scan3d<<<nb2, 512, 0, s2>>>(tot_new);
            k_fill  <<<NEDGE/256, 256, 0, s2>>>(nxt);
            cudaEventRecord(evJ[l], s2);

            k_gather_norm<<<(int)(((size_t)tot_new*(fo/4) + 255)/256), 256>>>(gw[l], gb[l], ga[l], tot_new, n, fo);
            cudaStreamWaitEvent(0, evJ[l], 0);
            A = pX;
        }
    }

    k_readout<<<NG, 256>>>(gw[2], gb[2], ga[2], nin[2]);
    k_final<<<(BATCH*512 + 255)/256, 256>>>(out);
}

// round 14
// speedup vs baseline: 1.4697x; 1.1118x over previous
#include <cuda_runtime.h>
#include <cuda_fp16.h>
#include <math.h>
#include <stdint.h>

// ---------------- problem constants ----------------
#define TS     8
#define BATCH  16
#define NPG    4096
#define NEDGE  (TS*BATCH*32768)
#define NG     (TS*BATCH)
#define EPSN   1e-5f
#define MAXN   524288

// ---------------- static device scratch ----------------
__device__ float g_S  [67108864];
__device__ float g_AGG[67108864];
__device__ float g_X  [33554432];
__device__ float g_DINV[MAXN];
__device__ float g_SCORE[MAXN];
__device__ int   g_MAP [MAXN];
__device__ int   g_PERMG[262144];
__device__ float g_GATE [262144];
__device__ int   g_CNT[MAXN];
__device__ int   g_CUR[MAXN];
__device__ int   g_ROW[MAXN];
__device__ int   g_BSUM[1024];
__device__ int   g_CSRC[NEDGE];
__device__ float g_CW [NEDGE];
__device__ int   g_ESRC[2][NEDGE];
__device__ int   g_EDST[2][NEDGE];
__device__ int   g_ECNT[2];
__device__ float g_SP1[NG*256];     // invariant: zero between uses (finstats self-zeroes)
__device__ float g_SP2[NG*256];
__device__ float g_MU [NG*256];
__device__ float g_RS [NG*256];
__device__ float g_IPN;
__device__ float g_PMEAN[NG*256];
__device__ float g_PMAX [NG*256];

// ---------------- utility ----------------
__global__ void k_zero2i(int* a, int* b, int cnt){
    int i = blockIdx.x*blockDim.x + threadIdx.x;
    if (i < cnt){ a[i] = 0; b[i] = 0; }
}

__global__ void k_edge_init(const int* __restrict__ ei){
    int idx = blockIdx.x*blockDim.x + threadIdx.x;
    if (idx == 0){ g_ECNT[0] = NEDGE; g_ECNT[1] = 0; }
    if (idx >= NEDGE) return;
    const int E = 32768*BATCH;
    int t = idx / E, e = idx % E;
    int base = t * (BATCH*NPG);
    int s = ei[(size_t)t*2*E + e]     + base;
    int d = ei[(size_t)t*2*E + E + e] + base;
    g_ESRC[0][idx] = s;
    g_EDST[0][idx] = d;
    atomicAdd(&g_CNT[d], 1);
}

// ---------------- CSR build ----------------
__global__ void k_scan1(int n){
    __shared__ int sh[512];
    int i = blockIdx.x*512 + threadIdx.x;
    int v = (i < n) ? g_CNT[i] : 0;
    sh[threadIdx.x] = v;
    __syncthreads();
    for (int st = 1; st < 512; st <<= 1){
        int t = (threadIdx.x >= st) ? sh[threadIdx.x - st] : 0;
        __syncthreads();
        sh[threadIdx.x] += t;
        __syncthreads();
    }
    if (i < n) g_ROW[i] = sh[threadIdx.x] - v;
    if (threadIdx.x == 511) g_BSUM[blockIdx.x] = sh[511];
}
__global__ void k_scan3d(int n){
    __shared__ int sh[512];
    int bid = blockIdx.x, tid = threadIdx.x;
    int acc = 0;
    for (int j = tid; j < bid; j += 512) acc += g_BSUM[j];
    sh[tid] = acc;
    __syncthreads();
    for (int st = 256; st > 0; st >>= 1){
        if (tid < st) sh[tid] += sh[tid + st];
        __syncthreads();
    }
    int base = sh[0];
    int i = bid*512 + tid;
    if (i < n){
        g_ROW[i] += base;
        g_DINV[i] = rsqrtf(1.f + (float)g_CNT[i]);
    }
}

__global__ void k_fill(int cur){
    int e = blockIdx.x*blockDim.x + threadIdx.x;
    if (e >= g_ECNT[cur]) return;
    int s = g_ESRC[cur][e], d = g_EDST[cur][e];
    int slot = g_ROW[d] + atomicAdd(&g_CUR[d], 1);
    g_CSRC[slot] = s;
    g_CW[slot]   = g_DINV[s]*g_DINV[d];
}

// ---------------- aggregate-first ----------------
__global__ void k_aggregate(const float* __restrict__ X, int ntot, int f, int wpn){
    int gw = (blockIdx.x*blockDim.x + threadIdx.x) >> 5;
    int lane = threadIdx.x & 31;
    int node = gw / wpn;
    if (node >= ntot) return;
    int fb = (gw % wpn)*128 + lane*4;
    if (fb >= f) return;
    int r0 = g_ROW[node];
    int cnt = g_CNT[node];
    int eend = r0 + cnt;
    float ax0 = 0.f, ay0 = 0.f, az0 = 0.f, aw0 = 0.f;
    float ax1 = 0.f, ay1 = 0.f, az1 = 0.f, aw1 = 0.f;
    int e = r0;
    for (; e + 1 < eend; e += 2){
        int s0 = g_CSRC[e],   s1 = g_CSRC[e+1];
        float w0 = g_CW[e],   w1 = g_CW[e+1];
        float4 v0 = *(const float4*)&X[(size_t)s0*f + fb];
        float4 v1 = *(const float4*)&X[(size_t)s1*f + fb];
        ax0 += w0*v0.x; ay0 += w0*v0.y; az0 += w0*v0.z; aw0 += w0*v0.w;
        ax1 += w1*v1.x; ay1 += w1*v1.y; az1 += w1*v1.z; aw1 += w1*v1.w;
    }
    if (e < eend){
        int s0 = g_CSRC[e];
        float w0 = g_CW[e];
        float4 v0 = *(const float4*)&X[(size_t)s0*f + fb];
        ax0 += w0*v0.x; ay0 += w0*v0.y; az0 += w0*v0.z; aw0 += w0*v0.w;
    }
    float di = g_DINV[node];
    float c = di*di;
    float4 sv = *(const float4*)&X[(size_t)node*f + fb];
    float4 o = { ax0 + ax1 + c*sv.x, ay0 + ay1 + c*sv.y,
                 az0 + az1 + c*sv.z, aw0 + aw1 + c*sv.w };
    *(float4*)&g_S[(size_t)node*f + fb] = o;
}

// ---------------- fp16-split GEMM (m16n8k16) + fused bias + stats ---------------
// C = A[M,K] @ W[K,N] + bias; 3-term split hi*hi + lo*hi + hi*lo (residual ~2^-22).
// Smem: A and B both stored k-contiguous as half2, row stride 17 half2 (34 halves).
#define H2ST 17

__device__ __forceinline__ void mma16(float* d, uint32_t a0, uint32_t a1, uint32_t a2, uint32_t a3,
                                      uint32_t b0, uint32_t b1){
    asm volatile("mma.sync.aligned.m16n8k16.row.col.f32.f16.f16.f32 "
        "{%0,%1,%2,%3}, {%4,%5,%6,%7}, {%8,%9}, {%0,%1,%2,%3};"
        : "+f"(d[0]), "+f"(d[1]), "+f"(d[2]), "+f"(d[3])
        : "r"(a0), "r"(a1), "r"(a2), "r"(a3), "r"(b0), "r"(b1));
}

__global__ void __launch_bounds__(256) k_gemm_tc(const float* __restrict__ A,
                                                 const float* __restrict__ W,
                                                 const float* __restrict__ bias,
                                                 float* __restrict__ C,
                                                 int M, int N, int K, int npg){
    __shared__ __half2 Ah2[128*H2ST];
    __shared__ __half2 Al2[128*H2ST];
    __shared__ __half2 Bh2[128*H2ST];
    __shared__ __half2 Bl2[128*H2ST];
    const int tid = threadIdx.x, lane = tid & 31, wid = tid >> 5;
    const int wm = (wid >> 1)*32, wn = (wid & 1)*64;
    const int bm = blockIdx.y*128, bn = blockIdx.x*128;
    const int g4 = lane >> 2, t4 = lane & 3;

    float acc[2][8][4] = {};

    const int K8 = ((K + 7)/8)*8;
    const int nch = (K8 + 31)/32;
    for (int kc = 0; kc < nch; kc++){
        const int k0 = kc*32;
        const int kend = min(32, K8 - k0);
        // stage A [128 rows x 16 half2]
        #pragma unroll
        for (int it = 0; it < 8; it++){
            int idx = it*256 + tid;
            int c = idx & 15, row = idx >> 4;
            int kg = k0 + c*2;
            float v0 = (kg   < K) ? A[(size_t)(bm+row)*K + kg]   : 0.f;
            float v1 = (kg+1 < K) ? A[(size_t)(bm+row)*K + kg+1] : 0.f;
            __half h0 = __float2half_rn(v0), h1 = __float2half_rn(v1);
            Ah2[row*H2ST + c] = __halves2half2(h0, h1);
            Al2[row*H2ST + c] = __halves2half2(__float2half_rn(v0 - __half2float(h0)),
                                               __float2half_rn(v1 - __half2float(h1)));
        }
        // stage B transposed: [128 n-rows x 16 half2 of k]
        #pragma unroll
        for (int it = 0; it < 8; it++){
            int idx = it*256 + tid;
            int n = idx & 127, kp = idx >> 7;   // kp in 0..15
            int kg = k0 + kp*2;
            float v0 = (kg   < K) ? W[(size_t)kg*N + bn + n]     : 0.f;
            float v1 = (kg+1 < K) ? W[(size_t)(kg+1)*N + bn + n] : 0.f;
            __half h0 = __float2half_rn(v0), h1 = __float2half_rn(v1);
            Bh2[n*H2ST + kp] = __halves2half2(h0, h1);
            Bl2[n*H2ST + kp] = __halves2half2(__float2half_rn(v0 - __half2float(h0)),
                                              __float2half_rn(v1 - __half2float(h1)));
        }
        __syncthreads();

        for (int kk = 0; kk < kend; kk += 16){
            int kh = kk >> 1;           // half2 offset
            uint32_t ah[2][4], al[2][4];
            #pragma unroll
            for (int ma = 0; ma < 2; ma++){
                int r0 = (wm + ma*16 + g4)*H2ST + kh + t4;
                ah[ma][0] = *(const uint32_t*)&Ah2[r0];
                ah[ma][1] = *(const uint32_t*)&Ah2[r0 + 8*H2ST];
                ah[ma][2] = *(const uint32_t*)&Ah2[r0 + 4];
                ah[ma][3] = *(const uint32_t*)&Ah2[r0 + 8*H2ST + 4];
                al[ma][0] = *(const uint32_t*)&Al2[r0];
                al[ma][1] = *(const uint32_t*)&Al2[r0 + 8*H2ST];
                al[ma][2] = *(const uint32_t*)&Al2[r0 + 4];
                al[ma][3] = *(const uint32_t*)&Al2[r0 + 8*H2ST + 4];
            }
            #pragma unroll
            for (int jn = 0; jn < 8; jn++){
                int cn = (wn + jn*8 + g4)*H2ST + kh + t4;
                uint32_t bh0 = *(const uint32_t*)&Bh2[cn];
                uint32_t bh1 = *(const uint32_t*)&Bh2[cn + 4];
                uint32_t bl0 = *(const uint32_t*)&Bl2[cn];
                uint32_t bl1 = *(const uint32_t*)&Bl2[cn + 4];
                #pragma unroll
                for (int ma = 0; ma < 2; ma++){
                    mma16(acc[ma][jn], ah[ma][0], ah[ma][1], ah[ma][2], ah[ma][3], bh0, bh1);
                    mma16(acc[ma][jn], al[ma][0], al[ma][1], al[ma][2], al[ma][3], bh0, bh1);
                    mma16(acc[ma][jn], ah[ma][0], ah[ma][1], ah[ma][2], ah[ma][3], bl0, bl1);
                }
            }
        }
        __syncthreads();
    }

    // epilogue: bias, store, per-column partial stats
    float ps[16], ps2[16];
    #pragma unroll
    for (int i = 0; i < 16; i++){ ps[i] = 0.f; ps2[i] = 0.f; }

    #pragma unroll
    for (int ma = 0; ma < 2; ma++){
        #pragma unroll
        for (int jn = 0; jn < 8; jn++){
            size_t row0 = (size_t)bm + wm + ma*16 + g4;
            int    colb = bn + wn + jn*8 + t4*2;
            float2 bv = *(const float2*)&bias[colb];
            float a0 = acc[ma][jn][0] + bv.x, a1 = acc[ma][jn][1] + bv.y;
            float a2 = acc[ma][jn][2] + bv.x, a3 = acc[ma][jn][3] + bv.y;
            float2 lo = { a0, a1 };
            float2 hi = { a2, a3 };
            *(float2*)&C[row0*N + colb]     = lo;
            *(float2*)&C[(row0+8)*N + colb] = hi;
            ps [jn*2+0] += a0 + a2;
            ps [jn*2+1] += a1 + a3;
            ps2[jn*2+0] += a0*a0 + a2*a2;
            ps2[jn*2+1] += a1*a1 + a3*a3;
        }
    }
    #pragma unroll
    for (int o = 4; o < 32; o <<= 1){
        #pragma unroll
        for (int i = 0; i < 16; i++){
            ps [i] += __shfl_xor_sync(0xFFFFFFFF, ps [i], o);
            ps2[i] += __shfl_xor_sync(0xFFFFFFFF, ps2[i], o);
        }
    }
    if (lane < 4){
        int g = bm / npg;
        #pragma unroll
        for (int i = 0; i < 16; i++){
            int colg = bn + wn + (i >> 1)*8 + t4*2 + (i & 1);
            atomicAdd(&g_SP1[g*256 + colg], ps[i]);
            atomicAdd(&g_SP2[g*256 + colg], ps2[i]);
        }
    }
}

// ---------------- finalize stats (+ pw norm), self-zero partials ----------------
__global__ void k_finstats(const float* __restrict__ ga, const float* __restrict__ pw,
                           int n, int f){
    int i = blockIdx.x*blockDim.x + threadIdx.x;
    if (i < NG*256){
        int fi = i & 255;
        if (fi < f){
            float s = g_SP1[i], s2 = g_SP2[i];
            g_SP1[i] = 0.f; g_SP2[i] = 0.f;
            float inv_n = 1.f/(float)n;
            float mu = s*inv_n;
            float m2 = s2*inv_n;
            float a = ga[fi];
            float var = m2 - mu*mu*a*(2.f - a);
            g_MU[i] = mu;
            g_RS[i] = rsqrtf(fmaxf(var, 0.f) + EPSN);
        }
    }
    if (blockIdx.x == 0){
        __shared__ float sh[256];
        float v = (threadIdx.x < f) ? pw[threadIdx.x] : 0.f;
        sh[threadIdx.x] = v*v;
        __syncthreads();
        for (int st = 128; st > 0; st >>= 1){
            if (threadIdx.x < st) sh[threadIdx.x] += sh[threadIdx.x + st];
            __syncthreads();
        }
        if (threadIdx.x == 0) g_IPN = rsqrtf(sh[0]);
    }
}

// ---------------- score ----------------
__global__ void k_score(const float* __restrict__ gw, const float* __restrict__ gb,
                        const float* __restrict__ ga, const float* __restrict__ pw,
                        int ntot, int n, int f){
    int node = (blockIdx.x*blockDim.x + threadIdx.x) >> 5;
    int lane = threadIdx.x & 31;
    if (node >= ntot) return;
    int g = node / n;
    float dot = 0.f;
    for (int fc = lane*4; fc < f; fc += 128){
        float4 v  = *(const float4*)&g_AGG[(size_t)node*f + fc];
        float4 mu = *(const float4*)&g_MU[g*256 + fc];
        float4 rs = *(const float4*)&g_RS[g*256 + fc];
        float4 w  = *(const float4*)&gw[fc];
        float4 b  = *(const float4*)&gb[fc];
        float4 a  = *(const float4*)&ga[fc];
        float4 p  = *(const float4*)&pw[fc];
        float x0 = fmaxf(w.x*(v.x - a.x*mu.x)*rs.x + b.x, 0.f);
        float x1 = fmaxf(w.y*(v.y - a.y*mu.y)*rs.y + b.y, 0.f);
        float x2 = fmaxf(w.z*(v.z - a.z*mu.z)*rs.z + b.z, 0.f);
        float x3 = fmaxf(w.w*(v.w - a.w*mu.w)*rs.w + b.w, 0.f);
        dot += x0*p.x + x1*p.y + x2*p.z + x3*p.w;
    }
    #pragma unroll
    for (int o = 16; o > 0; o >>= 1) dot += __shfl_xor_sync(0xFFFFFFFF, dot, o);
    if (lane == 0) g_SCORE[node] = tanhf(dot*g_IPN);
}

// ---------------- per-graph exact top-k (ballot/popc compaction) ----------------
__global__ void k_topk(int n, int k, int nxt){
    __shared__ unsigned keys[4096];
    __shared__ int hist[256];
    __shared__ unsigned sh_prefix;
    __shared__ int sh_rem;
    __shared__ int wgs[16], wes[16];
    __shared__ int tot_g, tot_e;
    __shared__ int base_g, base_e;

    int g = blockIdx.x;
    int tid = threadIdx.x;
    int wid = tid >> 5, lane = tid & 31;
    unsigned lmask = (1u << lane) - 1u;
    if (g == 0 && tid == 0) g_ECNT[nxt] = 0;
    const float* sc = g_SCORE + (size_t)g*n;

    for (int i = tid; i < n; i += blockDim.x){
        unsigned u = __float_as_uint(sc[i]);
        u = (u & 0x80000000u) ? ~u : (u | 0x80000000u);
        keys[i] = u;
    }
    if (tid == 0){ sh_prefix = 0u; sh_rem = k; }
    __syncthreads();

    for (int shift = 24; shift >= 0; shift -= 8){
        for (int i = tid; i < 256; i += blockDim.x) hist[i] = 0;
        __syncthreads();
        unsigned pmask = (shift == 24) ? 0u : (0xFFFFFFFFu << (shift + 8));
        unsigned pref = sh_prefix;
        for (int i = tid; i < n; i += blockDim.x){
            unsigned u = keys[i];
            if ((u & pmask) == pref) atomicAdd(&hist[(u >> shift) & 0xFF], 1);
        }
        __syncthreads();
        if (tid == 0){
            int rem = sh_rem, b;
            for (b = 255; b >= 0; b--){
                if (rem <= hist[b]) break;
                rem -= hist[b];
            }
            sh_prefix |= ((unsigned)b) << shift;
            sh_rem = rem;
        }
        __syncthreads();
    }
    unsigned thr = sh_prefix;
    int need = sh_rem;
    if (tid == 0){ base_g = 0; base_e = 0; }
    __syncthreads();

    for (int c0 = 0; c0 < n; c0 += blockDim.x){
        int i = c0 + tid;
        int gf = 0, ef = 0;
        if (i < n){
            unsigned u = keys[i];
            gf = (u > thr);
            ef = (u == thr);
        }
        unsigned bg = __ballot_sync(0xFFFFFFFF, gf);
        unsigned be = __ballot_sync(0xFFFFFFFF, ef);
        int pg = __popc(bg & lmask);
        int pe = __popc(be & lmask);
        if (lane == 0){ wgs[wid] = __popc(bg); wes[wid] = __popc(be); }
        __syncthreads();
        if (tid < 16){
            int vg = wgs[tid], ve = wes[tid];
            int ig = vg, ie = ve;
            #pragma unroll
            for (int o = 1; o < 16; o <<= 1){
                int t = __shfl_up_sync(0xFFFFu, ig, o); if (lane >= o) ig += t;
                t = __shfl_up_sync(0xFFFFu, ie, o);     if (lane >= o) ie += t;
            }
            wgs[tid] = ig - vg;
            wes[tid] = ie - ve;
            if (tid == 15){ tot_g = ig; tot_e = ie; }
        }
        __syncthreads();
        if (i < n){
            int g_before = base_g + wgs[wid] + pg;
            int e_before = base_e + wes[wid] + pe;
            bool kept = gf || (ef && (e_before < need));
            int oldg = g*n + i;
            if (kept){
                int newlocal = g_before + min(e_before, need);
                int newglobal = g*k + newlocal;
                g_MAP[oldg]        = newglobal;
                g_PERMG[newglobal] = oldg;
                g_GATE[newglobal]  = sc[i];
            } else {
                g_MAP[oldg] = -1;
            }
        }
        __syncthreads();
        if (tid == 0){ base_g += tot_g; base_e += tot_e; }
        __syncthreads();
    }
}

// ---------------- gather kept nodes with fused norm+relu+gate (layers 1,2) ------
__global__ void k_gather_norm(const float* __restrict__ gw, const float* __restrict__ gb,
                              const float* __restrict__ ga,
                              int tot_new, int n, int f){
    int per = f >> 2;
    size_t idx = (size_t)blockIdx.x*blockDim.x + threadIdx.x;
    if (idx >= (size_t)tot_new*per) return;
    int j  = (int)(idx / per);
    int fc = (int)(idx % per)*4;
    int old = g_PERMG[j];
    int g = old / n;
    float gv = g_GATE[j];
    float4 v  = *(const float4*)&g_AGG[(size_t)old*f + fc];
    float4 mu = *(const float4*)&g_MU[g*256 + fc];
    float4 rs = *(const float4*)&g_RS[g*256 + fc];
    float4 w  = *(const float4*)&gw[fc];
    float4 b  = *(const float4*)&gb[fc];
    float4 a  = *(const float4*)&ga[fc];
    float4 o;
    o.x = fmaxf(w.x*(v.x - a.x*mu.x)*rs.x + b.x, 0.f)*gv;
    o.y = fmaxf(w.y*(v.y - a.y*mu.y)*rs.y + b.y, 0.f)*gv;
    o.z = fmaxf(w.z*(v.z - a.z*mu.z)*rs.z + b.z, 0.f)*gv;
    o.w = fmaxf(w.w*(v.w - a.w*mu.w)*rs.w + b.w, 0.f)*gv;
    *(float4*)&g_X[(size_t)j*f + fc] = o;
}

// ---------------- remap + compact edges + count next in-degrees ----------------
__global__ void k_remap(int cur){
    int e = blockIdx.x*blockDim.x + threadIdx.x;
    if (e >= g_ECNT[cur]) return;
    int s = g_MAP[g_ESRC[cur][e]];
    int d = g_MAP[g_EDST[cur][e]];
    if (s >= 0 && d >= 0){
        int p = atomicAdd(&g_ECNT[cur^1], 1);
        g_ESRC[cur^1][p] = s;
        g_EDST[cur^1][p] = d;
        atomicAdd(&g_CNT[d], 1);
    }
}

// ---------------- fused L3 gather + readout ----------------
__global__ void k_readout(const float* __restrict__ gw, const float* __restrict__ gb,
                          const float* __restrict__ ga, int n){
    int gg = blockIdx.x;
    int f  = threadIdx.x;
    float w = gw[f], b = gb[f], a = ga[f];
    float mu = g_MU[gg*256 + f], rs = g_RS[gg*256 + f];
    float s = 0.f, mx = -INFINITY;
    for (int i = 0; i < 512; i++){
        int j = gg*512 + i;
        int old = g_PERMG[j];
        float gv = g_GATE[j];
        float v = g_AGG[(size_t)old*256 + f];
        float x = fmaxf(w*(v - a*mu)*rs + b, 0.f)*gv;
        s += x;
        mx = fmaxf(mx, x);
    }
    g_PMEAN[gg*256 + f] = s*(1.f/512.f);
    g_PMAX [gg*256 + f] = mx;
}

__global__ void k_final(float* __restrict__ out){
    int idx = blockIdx.x*blockDim.x + threadIdx.x;
    if (idx >= BATCH*512) return;
    int b = idx / 512, c = idx % 512;
    float acc = 0.f;
    if (c < 256){
        for (int t = 0; t < TS; t++) acc += g_PMEAN[(t*BATCH + b)*256 + c];
    } else {
        for (int t = 0; t < TS; t++) acc += g_PMAX[(t*BATCH + b)*256 + (c-256)];
    }
    out[idx] = acc*(1.f/(float)TS);
}

// ---------------- host orchestration ----------------
extern "C" void kernel_launch(void* const* d_in, const int* in_sizes, int n_in,
                              void* d_out, int out_size){
    const float* x_seq = (const float*)d_in[0];
    const int*   ei    = (const int*)  d_in[1];
    const float* W [3] = {(const float*)d_in[2],  (const float*)d_in[4],  (const float*)d_in[6]};
    const float* bb[3] = {(const float*)d_in[3],  (const float*)d_in[5],  (const float*)d_in[7]};
    const float* gw[3] = {(const float*)d_in[8],  (const float*)d_in[11], (const float*)d_in[14]};
    const float* gb[3] = {(const float*)d_in[9],  (const float*)d_in[12], (const float*)d_in[15]};
    const float* ga[3] = {(const float*)d_in[10], (const float*)d_in[13], (const float*)d_in[16]};
    const float* pw[3] = {(const float*)d_in[17], (const float*)d_in[18], (const float*)d_in[19]};
    float* out = (float*)d_out;

    float *pS, *pX, *pAGG;
    int *pCNT, *pCUR;
    cudaGetSymbolAddress((void**)&pS,   g_S);
    cudaGetSymbolAddress((void**)&pX,   g_X);
    cudaGetSymbolAddress((void**)&pAGG, g_AGG);
    cudaGetSymbolAddress((void**)&pCNT, g_CNT);
    cudaGetSymbolAddress((void**)&pCUR, g_CUR);

    static cudaStream_t s2 = nullptr;
    static cudaEvent_t evF[2], evJ[2];
    if (!s2){
        cudaStreamCreate(&s2);
        for (int i = 0; i < 2; i++){
            cudaEventCreateWithFlags(&evF[i], cudaEventDisableTiming);
            cudaEventCreateWithFlags(&evJ[i], cudaEventDisableTiming);
        }
    }

    const int nin [3] = {4096, 2048, 1024};
    const int nk  [3] = {2048, 1024, 512};
    const int fin [3] = {100, 128, 128};
    const int fout[3] = {128, 128, 256};

    k_zero2i<<<(NG*NPG + 255)/256, 256>>>(pCNT, pCUR, NG*NPG);
    k_edge_init<<<NEDGE/256, 256>>>(ei);
    k_scan1 <<<NG*NPG/512, 512>>>(NG*NPG);
    k_scan3d<<<NG*NPG/512, 512>>>(NG*NPG);
    k_fill  <<<NEDGE/256, 256>>>(0);

    const float* A = x_seq;
    for (int l = 0; l < 3; l++){
        int n = nin[l], k = nk[l], fi = fin[l], fo = fout[l];
        int ntot = NG * n;
        int cur = l & 1, nxt = cur ^ 1;
        int wpn = (fi + 127)/128;

        k_aggregate<<<ntot*wpn/8, 256>>>(A, ntot, fi, wpn);
        k_gemm_tc<<<dim3(fo/128, ntot/128), 256>>>(pS, W[l], bb[l], pAGG, ntot, fo, fi, n);

        k_finstats<<<(NG*256 + 255)/256, 256>>>(ga[l], pw[l], n, fo);
        k_score<<<ntot/8, 256>>>(gw[l], gb[l], ga[l], pw[l], ntot, n, fo);

        k_topk<<<NG, 512>>>(n, k, nxt);

        if (l < 2){
            int tot_new = NG * k;
            int nb2 = tot_new / 512;
            cudaEventRecord(evF[l], 0);
            cudaStreamWaitEvent(s2, evF[l], 0);
            k_zero2i<<<(tot_new + 255)/256, 256, 0, s2>>>(pCNT, pCUR, tot_new);
            k_remap <<<NEDGE/256, 256, 0, s2>>>(cur);
            k_scan1 <<<nb2, 512, 0, s2>>>(tot_new);
            k_scan3d<<<nb2, 512, 0, s2>>>(tot_new);
            k_fill  <<<NEDGE/256, 256, 0, s2>>>(nxt);
            cudaEventRecord(evJ[l], s2);

            k_gather_norm<<<(int)(((size_t)tot_new*(fo/4) + 255)/256), 256>>>(gw[l], gb[l], ga[l], tot_new, n, fo);
            cudaStreamWaitEvent(0, evJ[l], 0);
            A = pX;
        }
    }

    k_readout<<<NG, 256>>>(gw[2], gb[2], ga[2], nin[2]);
    k_final<<<(BATCH*512 + 255)/256, 256>>>(out);
}

// round 15
// speedup vs baseline: 1.4840x; 1.0097x over previous
#include <cuda_runtime.h>
#include <cuda_fp16.h>
#include <math.h>
#include <stdint.h>

// ---------------- problem constants ----------------
#define TS     8
#define BATCH  16
#define NPG    4096
#define NEDGE  (TS*BATCH*32768)
#define NG     (TS*BATCH)
#define EPSN   1e-5f
#define MAXN   524288

// ---------------- static device scratch ----------------
__device__ float g_S  [67108864];
__device__ float g_AGG[67108864];
__device__ float g_X  [33554432];
__device__ float g_DINV[MAXN];
__device__ float g_SCORE[MAXN];
__device__ int   g_MAP [MAXN];
__device__ int   g_PERMG[262144];
__device__ float g_GATE [262144];
__device__ int   g_CNT[MAXN];
__device__ int   g_ROW[MAXN];       // after fill: row END (start = end - cnt)
__device__ int   g_BSUM[1024];
__device__ int2  g_CSW[NEDGE];      // packed {src, coef-bits}
__device__ int   g_ESRC[2][NEDGE];
__device__ int   g_EDST[2][NEDGE];
__device__ int   g_ECNT[2];
__device__ float g_SP1[NG*256];     // invariant: zero between uses (finstats self-zeroes)
__device__ float g_SP2[NG*256];
__device__ float g_MU [NG*256];
__device__ float g_RS [NG*256];
__device__ float g_IPN;
__device__ float g_PMEAN[NG*256];
__device__ float g_PMAX [NG*256];

// ---------------- utility ----------------
__global__ void k_zeroi(int* a, int cnt){
    int i = blockIdx.x*blockDim.x + threadIdx.x;
    if (i < cnt) a[i] = 0;
}

__global__ void k_edge_init(const int* __restrict__ ei){
    int idx = blockIdx.x*blockDim.x + threadIdx.x;
    if (idx == 0){ g_ECNT[0] = NEDGE; g_ECNT[1] = 0; }
    if (idx >= NEDGE) return;
    const int E = 32768*BATCH;
    int t = idx / E, e = idx % E;
    int base = t * (BATCH*NPG);
    int s = ei[(size_t)t*2*E + e]     + base;
    int d = ei[(size_t)t*2*E + E + e] + base;
    g_ESRC[0][idx] = s;
    g_EDST[0][idx] = d;
    atomicAdd(&g_CNT[d], 1);
}

// ---------------- CSR build ----------------
__global__ void k_scan1(int n){
    __shared__ int sh[512];
    int i = blockIdx.x*512 + threadIdx.x;
    int v = (i < n) ? g_CNT[i] : 0;
    sh[threadIdx.x] = v;
    __syncthreads();
    for (int st = 1; st < 512; st <<= 1){
        int t = (threadIdx.x >= st) ? sh[threadIdx.x - st] : 0;
        __syncthreads();
        sh[threadIdx.x] += t;
        __syncthreads();
    }
    if (i < n) g_ROW[i] = sh[threadIdx.x] - v;
    if (threadIdx.x == 511) g_BSUM[blockIdx.x] = sh[511];
}
__global__ void k_scan3d(int n){
    __shared__ int sh[512];
    int bid = blockIdx.x, tid = threadIdx.x;
    int acc = 0;
    for (int j = tid; j < bid; j += 512) acc += g_BSUM[j];
    sh[tid] = acc;
    __syncthreads();
    for (int st = 256; st > 0; st >>= 1){
        if (tid < st) sh[tid] += sh[tid + st];
        __syncthreads();
    }
    int base = sh[0];
    int i = bid*512 + tid;
    if (i < n){
        g_ROW[i] += base;
        g_DINV[i] = rsqrtf(1.f + (float)g_CNT[i]);
    }
}

// fill: cursor = ROW itself (post-fill ROW[d] = row end)
__global__ void k_fill(int cur){
    int e = blockIdx.x*blockDim.x + threadIdx.x;
    if (e >= g_ECNT[cur]) return;
    int s = g_ESRC[cur][e], d = g_EDST[cur][e];
    int slot = atomicAdd(&g_ROW[d], 1);
    g_CSW[slot] = make_int2(s, __float_as_int(g_DINV[s]*g_DINV[d]));
}

// ---------------- aggregate-first: start = ROW[node]-CNT[node], end = ROW[node] --
__global__ void k_aggregate(const float* __restrict__ X, int ntot, int f, int wpn){
    int gw = (blockIdx.x*blockDim.x + threadIdx.x) >> 5;
    int lane = threadIdx.x & 31;
    int node = gw / wpn;
    if (node >= ntot) return;
    int fb = (gw % wpn)*128 + lane*4;
    if (fb >= f) return;
    int eend = g_ROW[node];
    int cnt = g_CNT[node];
    int e = eend - cnt;
    float ax0 = 0.f, ay0 = 0.f, az0 = 0.f, aw0 = 0.f;
    float ax1 = 0.f, ay1 = 0.f, az1 = 0.f, aw1 = 0.f;
    for (; e + 1 < eend; e += 2){
        int2 p0 = g_CSW[e], p1 = g_CSW[e+1];
        float w0 = __int_as_float(p0.y), w1 = __int_as_float(p1.y);
        float4 v0 = *(const float4*)&X[(size_t)p0.x*f + fb];
        float4 v1 = *(const float4*)&X[(size_t)p1.x*f + fb];
        ax0 += w0*v0.x; ay0 += w0*v0.y; az0 += w0*v0.z; aw0 += w0*v0.w;
        ax1 += w1*v1.x; ay1 += w1*v1.y; az1 += w1*v1.z; aw1 += w1*v1.w;
    }
    if (e < eend){
        int2 p0 = g_CSW[e];
        float w0 = __int_as_float(p0.y);
        float4 v0 = *(const float4*)&X[(size_t)p0.x*f + fb];
        ax0 += w0*v0.x; ay0 += w0*v0.y; az0 += w0*v0.z; aw0 += w0*v0.w;
    }
    float di = g_DINV[node];
    float c = di*di;
    float4 sv = *(const float4*)&X[(size_t)node*f + fb];
    float4 o = { ax0 + ax1 + c*sv.x, ay0 + ay1 + c*sv.y,
                 az0 + az1 + c*sv.z, aw0 + aw1 + c*sv.w };
    *(float4*)&g_S[(size_t)node*f + fb] = o;
}

// ---------------- fp16-split GEMM (m16n8k16) + fused bias + stats ---------------
#define H2ST 17

__device__ __forceinline__ void mma16(float* d, uint32_t a0, uint32_t a1, uint32_t a2, uint32_t a3,
                                      uint32_t b0, uint32_t b1){
    asm volatile("mma.sync.aligned.m16n8k16.row.col.f32.f16.f16.f32 "
        "{%0,%1,%2,%3}, {%4,%5,%6,%7}, {%8,%9}, {%0,%1,%2,%3};"
        : "+f"(d[0]), "+f"(d[1]), "+f"(d[2]), "+f"(d[3])
        : "r"(a0), "r"(a1), "r"(a2), "r"(a3), "r"(b0), "r"(b1));
}

__global__ void __launch_bounds__(256) k_gemm_tc(const float* __restrict__ A,
                                                 const float* __restrict__ W,
                                                 const float* __restrict__ bias,
                                                 float* __restrict__ C,
                                                 int M, int N, int K, int npg){
    __shared__ __half2 Ah2[128*H2ST];
    __shared__ __half2 Al2[128*H2ST];
    __shared__ __half2 Bh2[128*H2ST];
    __shared__ __half2 Bl2[128*H2ST];
    const int tid = threadIdx.x, lane = tid & 31, wid = tid >> 5;
    const int wm = (wid >> 1)*32, wn = (wid & 1)*64;
    const int bm = blockIdx.y*128, bn = blockIdx.x*128;
    const int g4 = lane >> 2, t4 = lane & 3;

    float acc[2][8][4] = {};

    const int K8 = ((K + 7)/8)*8;
    const int nch = (K8 + 31)/32;
    for (int kc = 0; kc < nch; kc++){
        const int k0 = kc*32;
        const int kend = min(32, K8 - k0);
        #pragma unroll
        for (int it = 0; it < 8; it++){
            int idx = it*256 + tid;
            int c = idx & 15, row = idx >> 4;
            int kg = k0 + c*2;
            float v0 = (kg   < K) ? A[(size_t)(bm+row)*K + kg]   : 0.f;
            float v1 = (kg+1 < K) ? A[(size_t)(bm+row)*K + kg+1] : 0.f;
            __half h0 = __float2half_rn(v0), h1 = __float2half_rn(v1);
            Ah2[row*H2ST + c] = __halves2half2(h0, h1);
            Al2[row*H2ST + c] = __halves2half2(__float2half_rn(v0 - __half2float(h0)),
                                               __float2half_rn(v1 - __half2float(h1)));
        }
        #pragma unroll
        for (int it = 0; it < 8; it++){
            int idx = it*256 + tid;
            int n = idx & 127, kp = idx >> 7;
            int kg = k0 + kp*2;
            float v0 = (kg   < K) ? W[(size_t)kg*N + bn + n]     : 0.f;
            float v1 = (kg+1 < K) ? W[(size_t)(kg+1)*N + bn + n] : 0.f;
            __half h0 = __float2half_rn(v0), h1 = __float2half_rn(v1);
            Bh2[n*H2ST + kp] = __halves2half2(h0, h1);
            Bl2[n*H2ST + kp] = __halves2half2(__float2half_rn(v0 - __half2float(h0)),
                                              __float2half_rn(v1 - __half2float(h1)));
        }
        __syncthreads();

        for (int kk = 0; kk < kend; kk += 16){
            int kh = kk >> 1;
            uint32_t ah[2][4], al[2][4];
            #pragma unroll
            for (int ma = 0; ma < 2; ma++){
                int r0 = (wm + ma*16 + g4)*H2ST + kh + t4;
                ah[ma][0] = *(const uint32_t*)&Ah2[r0];
                ah[ma][1] = *(const uint32_t*)&Ah2[r0 + 8*H2ST];
                ah[ma][2] = *(const uint32_t*)&Ah2[r0 + 4];
                ah[ma][3] = *(const uint32_t*)&Ah2[r0 + 8*H2ST + 4];
                al[ma][0] = *(const uint32_t*)&Al2[r0];
                al[ma][1] = *(const uint32_t*)&Al2[r0 + 8*H2ST];
                al[ma][2] = *(const uint32_t*)&Al2[r0 + 4];
                al[ma][3] = *(const uint32_t*)&Al2[r0 + 8*H2ST + 4];
            }
            #pragma unroll
            for (int jn = 0; jn < 8; jn++){
                int cn = (wn + jn*8 + g4)*H2ST + kh + t4;
                uint32_t bh0 = *(const uint32_t*)&Bh2[cn];
                uint32_t bh1 = *(const uint32_t*)&Bh2[cn + 4];
                uint32_t bl0 = *(const uint32_t*)&Bl2[cn];
                uint32_t bl1 = *(const uint32_t*)&Bl2[cn + 4];
                #pragma unroll
                for (int ma = 0; ma < 2; ma++){
                    mma16(acc[ma][jn], ah[ma][0], ah[ma][1], ah[ma][2], ah[ma][3], bh0, bh1);
                    mma16(acc[ma][jn], al[ma][0], al[ma][1], al[ma][2], al[ma][3], bh0, bh1);
                    mma16(acc[ma][jn], ah[ma][0], ah[ma][1], ah[ma][2], ah[ma][3], bl0, bl1);
                }
            }
        }
        __syncthreads();
    }

    float ps[16], ps2[16];
    #pragma unroll
    for (int i = 0; i < 16; i++){ ps[i] = 0.f; ps2[i] = 0.f; }

    #pragma unroll
    for (int ma = 0; ma < 2; ma++){
        #pragma unroll
        for (int jn = 0; jn < 8; jn++){
            size_t row0 = (size_t)bm + wm + ma*16 + g4;
            int    colb = bn + wn + jn*8 + t4*2;
            float2 bv = *(const float2*)&bias[colb];
            float a0 = acc[ma][jn][0] + bv.x, a1 = acc[ma][jn][1] + bv.y;
            float a2 = acc[ma][jn][2] + bv.x, a3 = acc[ma][jn][3] + bv.y;
            float2 lo = { a0, a1 };
            float2 hi = { a2, a3 };
            *(float2*)&C[row0*N + colb]     = lo;
            *(float2*)&C[(row0+8)*N + colb] = hi;
            ps [jn*2+0] += a0 + a2;
            ps [jn*2+1] += a1 + a3;
            ps2[jn*2+0] += a0*a0 + a2*a2;
            ps2[jn*2+1] += a1*a1 + a3*a3;
        }
    }
    #pragma unroll
    for (int o = 4; o < 32; o <<= 1){
        #pragma unroll
        for (int i = 0; i < 16; i++){
            ps [i] += __shfl_xor_sync(0xFFFFFFFF, ps [i], o);
            ps2[i] += __shfl_xor_sync(0xFFFFFFFF, ps2[i], o);
        }
    }
    if (lane < 4){
        int g = bm / npg;
        #pragma unroll
        for (int i = 0; i < 16; i++){
            int colg = bn + wn + (i >> 1)*8 + t4*2 + (i & 1);
            atomicAdd(&g_SP1[g*256 + colg], ps[i]);
            atomicAdd(&g_SP2[g*256 + colg], ps2[i]);
        }
    }
}

// ---------------- finalize stats (+ pw norm), self-zero partials ----------------
__global__ void k_finstats(const float* __restrict__ ga, const float* __restrict__ pw,
                           int n, int f){
    int i = blockIdx.x*blockDim.x + threadIdx.x;
    if (i < NG*256){
        int fi = i & 255;
        if (fi < f){
            float s = g_SP1[i], s2 = g_SP2[i];
            g_SP1[i] = 0.f; g_SP2[i] = 0.f;
            float inv_n = 1.f/(float)n;
            float mu = s*inv_n;
            float m2 = s2*inv_n;
            float a = ga[fi];
            float var = m2 - mu*mu*a*(2.f - a);
            g_MU[i] = mu;
            g_RS[i] = rsqrtf(fmaxf(var, 0.f) + EPSN);
        }
    }
    if (blockIdx.x == 0){
        __shared__ float sh[256];
        float v = (threadIdx.x < f) ? pw[threadIdx.x] : 0.f;
        sh[threadIdx.x] = v*v;
        __syncthreads();
        for (int st = 128; st > 0; st >>= 1){
            if (threadIdx.x < st) sh[threadIdx.x] += sh[threadIdx.x + st];
            __syncthreads();
        }
        if (threadIdx.x == 0) g_IPN = rsqrtf(sh[0]);
    }
}

// ---------------- score ----------------
__global__ void k_score(const float* __restrict__ gw, const float* __restrict__ gb,
                        const float* __restrict__ ga, const float* __restrict__ pw,
                        int ntot, int n, int f){
    int node = (blockIdx.x*blockDim.x + threadIdx.x) >> 5;
    int lane = threadIdx.x & 31;
    if (node >= ntot) return;
    int g = node / n;
    float dot = 0.f;
    for (int fc = lane*4; fc < f; fc += 128){
        float4 v  = *(const float4*)&g_AGG[(size_t)node*f + fc];
        float4 mu = *(const float4*)&g_MU[g*256 + fc];
        float4 rs = *(const float4*)&g_RS[g*256 + fc];
        float4 w  = *(const float4*)&gw[fc];
        float4 b  = *(const float4*)&gb[fc];
        float4 a  = *(const float4*)&ga[fc];
        float4 p  = *(const float4*)&pw[fc];
        float x0 = fmaxf(w.x*(v.x - a.x*mu.x)*rs.x + b.x, 0.f);
        float x1 = fmaxf(w.y*(v.y - a.y*mu.y)*rs.y + b.y, 0.f);
        float x2 = fmaxf(w.z*(v.z - a.z*mu.z)*rs.z + b.z, 0.f);
        float x3 = fmaxf(w.w*(v.w - a.w*mu.w)*rs.w + b.w, 0.f);
        dot += x0*p.x + x1*p.y + x2*p.z + x3*p.w;
    }
    #pragma unroll
    for (int o = 16; o > 0; o >>= 1) dot += __shfl_xor_sync(0xFFFFFFFF, dot, o);
    if (lane == 0) g_SCORE[node] = tanhf(dot*g_IPN);
}

// ---------------- per-graph exact top-k (ballot/popc compaction) ----------------
__global__ void k_topk(int n, int k, int nxt){
    __shared__ unsigned keys[4096];
    __shared__ int hist[256];
    __shared__ unsigned sh_prefix;
    __shared__ int sh_rem;
    __shared__ int wgs[16], wes[16];
    __shared__ int tot_g, tot_e;
    __shared__ int base_g, base_e;

    int g = blockIdx.x;
    int tid = threadIdx.x;
    int wid = tid >> 5, lane = tid & 31;
    unsigned lmask = (1u << lane) - 1u;
    if (g == 0 && tid == 0) g_ECNT[nxt] = 0;
    const float* sc = g_SCORE + (size_t)g*n;

    for (int i = tid; i < n; i += blockDim.x){
        unsigned u = __float_as_uint(sc[i]);
        u = (u & 0x80000000u) ? ~u : (u | 0x80000000u);
        keys[i] = u;
    }
    if (tid == 0){ sh_prefix = 0u; sh_rem = k; }
    __syncthreads();

    for (int shift = 24; shift >= 0; shift -= 8){
        for (int i = tid; i < 256; i += blockDim.x) hist[i] = 0;
        __syncthreads();
        unsigned pmask = (shift == 24) ? 0u : (0xFFFFFFFFu << (shift + 8));
        unsigned pref = sh_prefix;
        for (int i = tid; i < n; i += blockDim.x){
            unsigned u = keys[i];
            if ((u & pmask) == pref) atomicAdd(&hist[(u >> shift) & 0xFF], 1);
        }
        __syncthreads();
        if (tid == 0){
            int rem = sh_rem, b;
            for (b = 255; b >= 0; b--){
                if (rem <= hist[b]) break;
                rem -= hist[b];
            }
            sh_prefix |= ((unsigned)b) << shift;
            sh_rem = rem;
        }
        __syncthreads();
    }
    unsigned thr = sh_prefix;
    int need = sh_rem;
    if (tid == 0){ base_g = 0; base_e = 0; }
    __syncthreads();

    for (int c0 = 0; c0 < n; c0 += blockDim.x){
        int i = c0 + tid;
        int gf = 0, ef = 0;
        if (i < n){
            unsigned u = keys[i];
            gf = (u > thr);
            ef = (u == thr);
        }
        unsigned bg = __ballot_sync(0xFFFFFFFF, gf);
        unsigned be = __ballot_sync(0xFFFFFFFF, ef);
        int pg = __popc(bg & lmask);
        int pe = __popc(be & lmask);
        if (lane == 0){ wgs[wid] = __popc(bg); wes[wid] = __popc(be); }
        __syncthreads();
        if (tid < 16){
            int vg = wgs[tid], ve = wes[tid];
            int ig = vg, ie = ve;
            #pragma unroll
            for (int o = 1; o < 16; o <<= 1){
                int t = __shfl_up_sync(0xFFFFu, ig, o); if (lane >= o) ig += t;
                t = __shfl_up_sync(0xFFFFu, ie, o);     if (lane >= o) ie += t;
            }
            wgs[tid] = ig - vg;
            wes[tid] = ie - ve;
            if (tid == 15){ tot_g = ig; tot_e = ie; }
        }
        __syncthreads();
        if (i < n){
            int g_before = base_g + wgs[wid] + pg;
            int e_before = base_e + wes[wid] + pe;
            bool kept = gf || (ef && (e_before < need));
            int oldg = g*n + i;
            if (kept){
                int newlocal = g_before + min(e_before, need);
                int newglobal = g*k + newlocal;
                g_MAP[oldg]        = newglobal;
                g_PERMG[newglobal] = oldg;
                g_GATE[newglobal]  = sc[i];
            } else {
                g_MAP[oldg] = -1;
            }
        }
        __syncthreads();
        if (tid == 0){ base_g += tot_g; base_e += tot_e; }
        __syncthreads();
    }
}

// ---------------- gather kept nodes with fused norm+relu+gate (layers 1,2) ------
__global__ void k_gather_norm(const float* __restrict__ gw, const float* __restrict__ gb,
                              const float* __restrict__ ga,
                              int tot_new, int n, int f){
    int per = f >> 2;
    size_t idx = (size_t)blockIdx.x*blockDim.x + threadIdx.x;
    if (idx >= (size_t)tot_new*per) return;
    int j  = (int)(idx / per);
    int fc = (int)(idx % per)*4;
    int old = g_PERMG[j];
    int g = old / n;
    float gv = g_GATE[j];
    float4 v  = *(const float4*)&g_AGG[(size_t)old*f + fc];
    float4 mu = *(const float4*)&g_MU[g*256 + fc];
    float4 rs = *(const float4*)&g_RS[g*256 + fc];
    float4 w  = *(const float4*)&gw[fc];
    float4 b  = *(const float4*)&gb[fc];
    float4 a  = *(const float4*)&ga[fc];
    float4 o;
    o.x = fmaxf(w.x*(v.x - a.x*mu.x)*rs.x + b.x, 0.f)*gv;
    o.y = fmaxf(w.y*(v.y - a.y*mu.y)*rs.y + b.y, 0.f)*gv;
    o.z = fmaxf(w.z*(v.z - a.z*mu.z)*rs.z + b.z, 0.f)*gv;
    o.w = fmaxf(w.w*(v.w - a.w*mu.w)*rs.w + b.w, 0.f)*gv;
    *(float4*)&g_X[(size_t)j*f + fc] = o;
}

// ---------------- remap + compact edges + count next in-degrees ----------------
__global__ void k_remap(int cur){
    int e = blockIdx.x*blockDim.x + threadIdx.x;
    if (e >= g_ECNT[cur]) return;
    int s = g_MAP[g_ESRC[cur][e]];
    int d = g_MAP[g_EDST[cur][e]];
    if (s >= 0 && d >= 0){
        int p = atomicAdd(&g_ECNT[cur^1], 1);
        g_ESRC[cur^1][p] = s;
        g_EDST[cur^1][p] = d;
        atomicAdd(&g_CNT[d], 1);
    }
}

// ---------------- fused L3 gather + readout ----------------
__global__ void k_readout(const float* __restrict__ gw, const float* __restrict__ gb,
                          const float* __restrict__ ga, int n){
    int gg = blockIdx.x;
    int f  = threadIdx.x;
    float w = gw[f], b = gb[f], a = ga[f];
    float mu = g_MU[gg*256 + f], rs = g_RS[gg*256 + f];
    float s = 0.f, mx = -INFINITY;
    for (int i = 0; i < 512; i++){
        int j = gg*512 + i;
        int old = g_PERMG[j];
        float gv = g_GATE[j];
        float v = g_AGG[(size_t)old*256 + f];
        float x = fmaxf(w*(v - a*mu)*rs + b, 0.f)*gv;
        s += x;
        mx = fmaxf(mx, x);
    }
    g_PMEAN[gg*256 + f] = s*(1.f/512.f);
    g_PMAX [gg*256 + f] = mx;
}

__global__ void k_final(float* __restrict__ out){
    int idx = blockIdx.x*blockDim.x + threadIdx.x;
    if (idx >= BATCH*512) return;
    int b = idx / 512, c = idx % 512;
    float acc = 0.f;
    if (c < 256){
        for (int t = 0; t < TS; t++) acc += g_PMEAN[(t*BATCH + b)*256 + c];
    } else {
        for (int t = 0; t < TS; t++) acc += g_PMAX[(t*BATCH + b)*256 + (c-256)];
    }
    out[idx] = acc*(1.f/(float)TS);
}

// ---------------- host orchestration ----------------
extern "C" void kernel_launch(void* const* d_in, const int* in_sizes, int n_in,
                              void* d_out, int out_size){
    const float* x_seq = (const float*)d_in[0];
    const int*   ei    = (const int*)  d_in[1];
    const float* W [3] = {(const float*)d_in[2],  (const float*)d_in[4],  (const float*)d_in[6]};
    const float* bb[3] = {(const float*)d_in[3],  (const float*)d_in[5],  (const float*)d_in[7]};
    const float* gw[3] = {(const float*)d_in[8],  (const float*)d_in[11], (const float*)d_in[14]};
    const float* gb[3] = {(const float*)d_in[9],  (const float*)d_in[12], (const float*)d_in[15]};
    const float* ga[3] = {(const float*)d_in[10], (const float*)d_in[13], (const float*)d_in[16]};
    const float* pw[3] = {(const float*)d_in[17], (const float*)d_in[18], (const float*)d_in[19]};
    float* out = (float*)d_out;

    float *pS, *pX, *pAGG;
    int *pCNT;
    cudaGetSymbolAddress((void**)&pS,   g_S);
    cudaGetSymbolAddress((void**)&pX,   g_X);
    cudaGetSymbolAddress((void**)&pAGG, g_AGG);
    cudaGetSymbolAddress((void**)&pCNT, g_CNT);

    static cudaStream_t s2 = nullptr;
    static cudaEvent_t evF[2], evJ[2];
    if (!s2){
        cudaStreamCreate(&s2);
        for (int i = 0; i < 2; i++){
            cudaEventCreateWithFlags(&evF[i], cudaEventDisableTiming);
            cudaEventCreateWithFlags(&evJ[i], cudaEventDisableTiming);
        }
    }

    const int nin [3] = {4096, 2048, 1024};
    const int nk  [3] = {2048, 1024, 512};
    const int fin [3] = {100, 128, 128};
    const int fout[3] = {128, 128, 256};

    k_zeroi<<<(NG*NPG + 255)/256, 256>>>(pCNT, NG*NPG);
    k_edge_init<<<NEDGE/256, 256>>>(ei);
    k_scan1 <<<NG*NPG/512, 512>>>(NG*NPG);
    k_scan3d<<<NG*NPG/512, 512>>>(NG*NPG);
    k_fill  <<<NEDGE/256, 256>>>(0);

    const float* A = x_seq;
    for (int l = 0; l < 3; l++){
        int n = nin[l], k = nk[l], fi = fin[l], fo = fout[l];
        int ntot = NG * n;
        int cur = l & 1, nxt = cur ^ 1;
        int wpn = (fi + 127)/128;

        k_aggregate<<<ntot*wpn/8, 256>>>(A, ntot, fi, wpn);
        k_gemm_tc<<<dim3(fo/128, ntot/128), 256>>>(pS, W[l], bb[l], pAGG, ntot, fo, fi, n);

        k_finstats<<<(NG*256 + 255)/256, 256>>>(ga[l], pw[l], n, fo);
        k_score<<<ntot/8, 256>>>(gw[l], gb[l], ga[l], pw[l], ntot, n, fo);

        k_topk<<<NG, 512>>>(n, k, nxt);

        if (l < 2){
            int tot_new = NG * k;
            int nb2 = tot_new / 512;
            cudaEventRecord(evF[l], 0);
            cudaStreamWaitEvent(s2, evF[l], 0);
            k_zeroi <<<(tot_new + 255)/256, 256, 0, s2>>>(pCNT, tot_new);
            k_remap <<<NEDGE/256, 256, 0, s2>>>(cur);
            k_scan1 <<<nb2, 512, 0, s2>>>(tot_new);
            k_scan3d<<<nb2, 512, 0, s2>>>(tot_new);
            k_fill  <<<NEDGE/256, 256, 0, s2>>>(nxt);
            cudaEventRecord(evJ[l], s2);

            k_gather_norm<<<(int)(((size_t)tot_new*(fo/4) + 255)/256), 256>>>(gw[l], gb[l], ga[l], tot_new, n, fo);
            cudaStreamWaitEvent(0, evJ[l], 0);
            A = pX;
        }
    }

    k_readout<<<NG, 256>>>(gw[2], gb[2], ga[2], nin[2]);
    k_final<<<(BATCH*512 + 255)/256, 256>>>(out);
}

// round 16
// speedup vs baseline: 1.5745x; 1.0610x over previous
#include <cuda_runtime.h>
#include <cuda_fp16.h>
#include <math.h>
#include <stdint.h>

// ---------------- problem constants ----------------
#define TS     8
#define BATCH  16
#define NPG    4096
#define NEDGE  (TS*BATCH*32768)
#define NG     (TS*BATCH)
#define EPSN   1e-5f
#define MAXN   524288

// ---------------- static device scratch ----------------
__device__ float g_S  [67108864];
__device__ float g_AGG[67108864];
__device__ float g_X  [33554432];
__device__ float g_DINV[MAXN];
__device__ float g_SCORE[MAXN];
__device__ int   g_MAP [MAXN];
__device__ int   g_PERMG[262144];
__device__ float g_GATE [262144];
__device__ int   g_CNT[MAXN];
__device__ int   g_ROW[MAXN];       // after fill: row END (start = end - cnt)
__device__ int   g_BSUM[1024];
__device__ int   g_CSRC[NEDGE];     // CSR: src node only (coef recomputed in aggregate)
__device__ int   g_ESRC[2][NEDGE];
__device__ int   g_EDST[2][NEDGE];
__device__ int   g_ECNT[2];
__device__ float g_SP1[NG*256];     // invariant: zero between uses (finstats self-zeroes)
__device__ float g_SP2[NG*256];
__device__ float g_MU [NG*256];
__device__ float g_RS [NG*256];
__device__ float g_IPN;
__device__ float g_PMEAN[4*NG*256]; // per-chunk partial sums
__device__ float g_PMAX [4*NG*256]; // per-chunk partial maxes

// ---------------- utility ----------------
__global__ void k_zeroi(int* a, int cnt){
    int i = blockIdx.x*blockDim.x + threadIdx.x;
    if (i < cnt) a[i] = 0;
}

__global__ void k_edge_init(const int* __restrict__ ei){
    int idx = blockIdx.x*blockDim.x + threadIdx.x;
    if (idx == 0){ g_ECNT[0] = NEDGE; g_ECNT[1] = 0; }
    if (idx >= NEDGE) return;
    const int E = 32768*BATCH;
    int t = idx / E, e = idx % E;
    int base = t * (BATCH*NPG);
    int s = ei[(size_t)t*2*E + e]     + base;
    int d = ei[(size_t)t*2*E + E + e] + base;
    g_ESRC[0][idx] = s;
    g_EDST[0][idx] = d;
    atomicAdd(&g_CNT[d], 1);
}

// ---------------- CSR build ----------------
__global__ void k_scan1(int n){
    __shared__ int sh[512];
    int i = blockIdx.x*512 + threadIdx.x;
    int v = (i < n) ? g_CNT[i] : 0;
    sh[threadIdx.x] = v;
    __syncthreads();
    for (int st = 1; st < 512; st <<= 1){
        int t = (threadIdx.x >= st) ? sh[threadIdx.x - st] : 0;
        __syncthreads();
        sh[threadIdx.x] += t;
        __syncthreads();
    }
    if (i < n) g_ROW[i] = sh[threadIdx.x] - v;
    if (threadIdx.x == 511) g_BSUM[blockIdx.x] = sh[511];
}
__global__ void k_scan3d(int n){
    __shared__ int sh[512];
    int bid = blockIdx.x, tid = threadIdx.x;
    int acc = 0;
    for (int j = tid; j < bid; j += 512) acc += g_BSUM[j];
    sh[tid] = acc;
    __syncthreads();
    for (int st = 256; st > 0; st >>= 1){
        if (tid < st) sh[tid] += sh[tid + st];
        __syncthreads();
    }
    int base = sh[0];
    int i = bid*512 + tid;
    if (i < n){
        g_ROW[i] += base;
        g_DINV[i] = rsqrtf(1.f + (float)g_CNT[i]);
    }
}

// fill: cursor = ROW itself (post-fill ROW[d] = row end); payload = src only
__global__ void k_fill(int cur){
    int e = blockIdx.x*blockDim.x + threadIdx.x;
    if (e >= g_ECNT[cur]) return;
    int s = g_ESRC[cur][e], d = g_EDST[cur][e];
    int slot = atomicAdd(&g_ROW[d], 1);
    g_CSRC[slot] = s;
}

// ---------------- aggregate-first: coef computed from DINV on the fly -----------
__global__ void k_aggregate(const float* __restrict__ X, int ntot, int f, int wpn){
    int gw = (blockIdx.x*blockDim.x + threadIdx.x) >> 5;
    int lane = threadIdx.x & 31;
    int node = gw / wpn;
    if (node >= ntot) return;
    int fb = (gw % wpn)*128 + lane*4;
    if (fb >= f) return;
    int eend = g_ROW[node];
    int cnt = g_CNT[node];
    int e = eend - cnt;
    float di = g_DINV[node];
    float ax0 = 0.f, ay0 = 0.f, az0 = 0.f, aw0 = 0.f;
    float ax1 = 0.f, ay1 = 0.f, az1 = 0.f, aw1 = 0.f;
    for (; e + 1 < eend; e += 2){
        int s0 = g_CSRC[e], s1 = g_CSRC[e+1];
        float w0 = g_DINV[s0]*di, w1 = g_DINV[s1]*di;
        float4 v0 = *(const float4*)&X[(size_t)s0*f + fb];
        float4 v1 = *(const float4*)&X[(size_t)s1*f + fb];
        ax0 += w0*v0.x; ay0 += w0*v0.y; az0 += w0*v0.z; aw0 += w0*v0.w;
        ax1 += w1*v1.x; ay1 += w1*v1.y; az1 += w1*v1.z; aw1 += w1*v1.w;
    }
    if (e < eend){
        int s0 = g_CSRC[e];
        float w0 = g_DINV[s0]*di;
        float4 v0 = *(const float4*)&X[(size_t)s0*f + fb];
        ax0 += w0*v0.x; ay0 += w0*v0.y; az0 += w0*v0.z; aw0 += w0*v0.w;
    }
    float c = di*di;
    float4 sv = *(const float4*)&X[(size_t)node*f + fb];
    float4 o = { ax0 + ax1 + c*sv.x, ay0 + ay1 + c*sv.y,
                 az0 + az1 + c*sv.z, aw0 + aw1 + c*sv.w };
    *(float4*)&g_S[(size_t)node*f + fb] = o;
}

// ---------------- fp16-split GEMM (m16n8k16) + fused bias + stats ---------------
#define H2ST 17

__device__ __forceinline__ void mma16(float* d, uint32_t a0, uint32_t a1, uint32_t a2, uint32_t a3,
                                      uint32_t b0, uint32_t b1){
    asm volatile("mma.sync.aligned.m16n8k16.row.col.f32.f16.f16.f32 "
        "{%0,%1,%2,%3}, {%4,%5,%6,%7}, {%8,%9}, {%0,%1,%2,%3};"
        : "+f"(d[0]), "+f"(d[1]), "+f"(d[2]), "+f"(d[3])
        : "r"(a0), "r"(a1), "r"(a2), "r"(a3), "r"(b0), "r"(b1));
}

__global__ void __launch_bounds__(256) k_gemm_tc(const float* __restrict__ A,
                                                 const float* __restrict__ W,
                                                 const float* __restrict__ bias,
                                                 float* __restrict__ C,
                                                 int M, int N, int K, int npg){
    __shared__ __half2 Ah2[128*H2ST];
    __shared__ __half2 Al2[128*H2ST];
    __shared__ __half2 Bh2[128*H2ST];
    __shared__ __half2 Bl2[128*H2ST];
    const int tid = threadIdx.x, lane = tid & 31, wid = tid >> 5;
    const int wm = (wid >> 1)*32, wn = (wid & 1)*64;
    const int bm = blockIdx.y*128, bn = blockIdx.x*128;
    const int g4 = lane >> 2, t4 = lane & 3;

    float acc[2][8][4] = {};

    const int K8 = ((K + 7)/8)*8;
    const int nch = (K8 + 31)/32;
    for (int kc = 0; kc < nch; kc++){
        const int k0 = kc*32;
        const int kend = min(32, K8 - k0);
        #pragma unroll
        for (int it = 0; it < 8; it++){
            int idx = it*256 + tid;
            int c = idx & 15, row = idx >> 4;
            int kg = k0 + c*2;
            float v0 = (kg   < K) ? A[(size_t)(bm+row)*K + kg]   : 0.f;
            float v1 = (kg+1 < K) ? A[(size_t)(bm+row)*K + kg+1] : 0.f;
            __half h0 = __float2half_rn(v0), h1 = __float2half_rn(v1);
            Ah2[row*H2ST + c] = __halves2half2(h0, h1);
            Al2[row*H2ST + c] = __halves2half2(__float2half_rn(v0 - __half2float(h0)),
                                               __float2half_rn(v1 - __half2float(h1)));
        }
        #pragma unroll
        for (int it = 0; it < 8; it++){
            int idx = it*256 + tid;
            int n = idx & 127, kp = idx >> 7;
            int kg = k0 + kp*2;
            float v0 = (kg   < K) ? W[(size_t)kg*N + bn + n]     : 0.f;
            float v1 = (kg+1 < K) ? W[(size_t)(kg+1)*N + bn + n] : 0.f;
            __half h0 = __float2half_rn(v0), h1 = __float2half_rn(v1);
            Bh2[n*H2ST + kp] = __halves2half2(h0, h1);
            Bl2[n*H2ST + kp] = __halves2half2(__float2half_rn(v0 - __half2float(h0)),
                                              __float2half_rn(v1 - __half2float(h1)));
        }
        __syncthreads();

        for (int kk = 0; kk < kend; kk += 16){
            int kh = kk >> 1;
            uint32_t ah[2][4], al[2][4];
            #pragma unroll
            for (int ma = 0; ma < 2; ma++){
                int r0 = (wm + ma*16 + g4)*H2ST + kh + t4;
                ah[ma][0] = *(const uint32_t*)&Ah2[r0];
                ah[ma][1] = *(const uint32_t*)&Ah2[r0 + 8*H2ST];
                ah[ma][2] = *(const uint32_t*)&Ah2[r0 + 4];
                ah[ma][3] = *(const uint32_t*)&Ah2[r0 + 8*H2ST + 4];
                al[ma][0] = *(const uint32_t*)&Al2[r0];
                al[ma][1] = *(const uint32_t*)&Al2[r0 + 8*H2ST];
                al[ma][2] = *(const uint32_t*)&Al2[r0 + 4];
                al[ma][3] = *(const uint32_t*)&Al2[r0 + 8*H2ST + 4];
            }
            #pragma unroll
            for (int jn = 0; jn < 8; jn++){
                int cn = (wn + jn*8 + g4)*H2ST + kh + t4;
                uint32_t bh0 = *(const uint32_t*)&Bh2[cn];
                uint32_t bh1 = *(const uint32_t*)&Bh2[cn + 4];
                uint32_t bl0 = *(const uint32_t*)&Bl2[cn];
                uint32_t bl1 = *(const uint32_t*)&Bl2[cn + 4];
                #pragma unroll
                for (int ma = 0; ma < 2; ma++){
                    mma16(acc[ma][jn], ah[ma][0], ah[ma][1], ah[ma][2], ah[ma][3], bh0, bh1);
                    mma16(acc[ma][jn], al[ma][0], al[ma][1], al[ma][2], al[ma][3], bh0, bh1);
                    mma16(acc[ma][jn], ah[ma][0], ah[ma][1], ah[ma][2], ah[ma][3], bl0, bl1);
                }
            }
        }
        __syncthreads();
    }

    float ps[16], ps2[16];
    #pragma unroll
    for (int i = 0; i < 16; i++){ ps[i] = 0.f; ps2[i] = 0.f; }

    #pragma unroll
    for (int ma = 0; ma < 2; ma++){
        #pragma unroll
        for (int jn = 0; jn < 8; jn++){
            size_t row0 = (size_t)bm + wm + ma*16 + g4;
            int    colb = bn + wn + jn*8 + t4*2;
            float2 bv = *(const float2*)&bias[colb];
            float a0 = acc[ma][jn][0] + bv.x, a1 = acc[ma][jn][1] + bv.y;
            float a2 = acc[ma][jn][2] + bv.x, a3 = acc[ma][jn][3] + bv.y;
            float2 lo = { a0, a1 };
            float2 hi = { a2, a3 };
            *(float2*)&C[row0*N + colb]     = lo;
            *(float2*)&C[(row0+8)*N + colb] = hi;
            ps [jn*2+0] += a0 + a2;
            ps [jn*2+1] += a1 + a3;
            ps2[jn*2+0] += a0*a0 + a2*a2;
            ps2[jn*2+1] += a1*a1 + a3*a3;
        }
    }
    #pragma unroll
    for (int o = 4; o < 32; o <<= 1){
        #pragma unroll
        for (int i = 0; i < 16; i++){
            ps [i] += __shfl_xor_sync(0xFFFFFFFF, ps [i], o);
            ps2[i] += __shfl_xor_sync(0xFFFFFFFF, ps2[i], o);
        }
    }
    if (lane < 4){
        int g = bm / npg;
        #pragma unroll
        for (int i = 0; i < 16; i++){
            int colg = bn + wn + (i >> 1)*8 + t4*2 + (i & 1);
            atomicAdd(&g_SP1[g*256 + colg], ps[i]);
            atomicAdd(&g_SP2[g*256 + colg], ps2[i]);
        }
    }
}

// ---------------- finalize stats (+ pw norm), self-zero partials ----------------
__global__ void k_finstats(const float* __restrict__ ga, const float* __restrict__ pw,
                           int n, int f){
    int i = blockIdx.x*blockDim.x + threadIdx.x;
    if (i < NG*256){
        int fi = i & 255;
        if (fi < f){
            float s = g_SP1[i], s2 = g_SP2[i];
            g_SP1[i] = 0.f; g_SP2[i] = 0.f;
            float inv_n = 1.f/(float)n;
            float mu = s*inv_n;
            float m2 = s2*inv_n;
            float a = ga[fi];
            float var = m2 - mu*mu*a*(2.f - a);
            g_MU[i] = mu;
            g_RS[i] = rsqrtf(fmaxf(var, 0.f) + EPSN);
        }
    }
    if (blockIdx.x == 0){
        __shared__ float sh[256];
        float v = (threadIdx.x < f) ? pw[threadIdx.x] : 0.f;
        sh[threadIdx.x] = v*v;
        __syncthreads();
        for (int st = 128; st > 0; st >>= 1){
            if (threadIdx.x < st) sh[threadIdx.x] += sh[threadIdx.x + st];
            __syncthreads();
        }
        if (threadIdx.x == 0) g_IPN = rsqrtf(sh[0]);
    }
}

// ---------------- score ----------------
__global__ void k_score(const float* __restrict__ gw, const float* __restrict__ gb,
                        const float* __restrict__ ga, const float* __restrict__ pw,
                        int ntot, int n, int f){
    int node = (blockIdx.x*blockDim.x + threadIdx.x) >> 5;
    int lane = threadIdx.x & 31;
    if (node >= ntot) return;
    int g = node / n;
    float dot = 0.f;
    for (int fc = lane*4; fc < f; fc += 128){
        float4 v  = *(const float4*)&g_AGG[(size_t)node*f + fc];
        float4 mu = *(const float4*)&g_MU[g*256 + fc];
        float4 rs = *(const float4*)&g_RS[g*256 + fc];
        float4 w  = *(const float4*)&gw[fc];
        float4 b  = *(const float4*)&gb[fc];
        float4 a  = *(const float4*)&ga[fc];
        float4 p  = *(const float4*)&pw[fc];
        float x0 = fmaxf(w.x*(v.x - a.x*mu.x)*rs.x + b.x, 0.f);
        float x1 = fmaxf(w.y*(v.y - a.y*mu.y)*rs.y + b.y, 0.f);
        float x2 = fmaxf(w.z*(v.z - a.z*mu.z)*rs.z + b.z, 0.f);
        float x3 = fmaxf(w.w*(v.w - a.w*mu.w)*rs.w + b.w, 0.f);
        dot += x0*p.x + x1*p.y + x2*p.z + x3*p.w;
    }
    #pragma unroll
    for (int o = 16; o > 0; o >>= 1) dot += __shfl_xor_sync(0xFFFFFFFF, dot, o);
    if (lane == 0) g_SCORE[node] = tanhf(dot*g_IPN);
}

// ---------------- per-graph exact top-k (ballot/popc compaction) ----------------
__global__ void k_topk(int n, int k, int nxt){
    __shared__ unsigned keys[4096];
    __shared__ int hist[256];
    __shared__ unsigned sh_prefix;
    __shared__ int sh_rem;
    __shared__ int wgs[16], wes[16];
    __shared__ int tot_g, tot_e;
    __shared__ int base_g, base_e;

    int g = blockIdx.x;
    int tid = threadIdx.x;
    int wid = tid >> 5, lane = tid & 31;
    unsigned lmask = (1u << lane) - 1u;
    if (g == 0 && tid == 0) g_ECNT[nxt] = 0;
    const float* sc = g_SCORE + (size_t)g*n;

    for (int i = tid; i < n; i += blockDim.x){
        unsigned u = __float_as_uint(sc[i]);
        u = (u & 0x80000000u) ? ~u : (u | 0x80000000u);
        keys[i] = u;
    }
    if (tid == 0){ sh_prefix = 0u; sh_rem = k; }
    __syncthreads();

    for (int shift = 24; shift >= 0; shift -= 8){
        for (int i = tid; i < 256; i += blockDim.x) hist[i] = 0;
        __syncthreads();
        unsigned pmask = (shift == 24) ? 0u : (0xFFFFFFFFu << (shift + 8));
        unsigned pref = sh_prefix;
        for (int i = tid; i < n; i += blockDim.x){
            unsigned u = keys[i];
            if ((u & pmask) == pref) atomicAdd(&hist[(u >> shift) & 0xFF], 1);
        }
        __syncthreads();
        if (tid == 0){
            int rem = sh_rem, b;
            for (b = 255; b >= 0; b--){
                if (rem <= hist[b]) break;
                rem -= hist[b];
            }
            sh_prefix |= ((unsigned)b) << shift;
            sh_rem = rem;
        }
        __syncthreads();
    }
    unsigned thr = sh_prefix;
    int need = sh_rem;
    if (tid == 0){ base_g = 0; base_e = 0; }
    __syncthreads();

    for (int c0 = 0; c0 < n; c0 += blockDim.x){
        int i = c0 + tid;
        int gf = 0, ef = 0;
        if (i < n){
            unsigned u = keys[i];
            gf = (u > thr);
            ef = (u == thr);
        }
        unsigned bg = __ballot_sync(0xFFFFFFFF, gf);
        unsigned be = __ballot_sync(0xFFFFFFFF, ef);
        int pg = __popc(bg & lmask);
        int pe = __popc(be & lmask);
        if (lane == 0){ wgs[wid] = __popc(bg); wes[wid] = __popc(be); }
        __syncthreads();
        if (tid < 16){
            int vg = wgs[tid], ve = wes[tid];
            int ig = vg, ie = ve;
            #pragma unroll
            for (int o = 1; o < 16; o <<= 1){
                int t = __shfl_up_sync(0xFFFFu, ig, o); if (lane >= o) ig += t;
                t = __shfl_up_sync(0xFFFFu, ie, o);     if (lane >= o) ie += t;
            }
            wgs[tid] = ig - vg;
            wes[tid] = ie - ve;
            if (tid == 15){ tot_g = ig; tot_e = ie; }
        }
        __syncthreads();
        if (i < n){
            int g_before = base_g + wgs[wid] + pg;
            int e_before = base_e + wes[wid] + pe;
            bool kept = gf || (ef && (e_before < need));
            int oldg = g*n + i;
            if (kept){
                int newlocal = g_before + min(e_before, need);
                int newglobal = g*k + newlocal;
                g_MAP[oldg]        = newglobal;
                g_PERMG[newglobal] = oldg;
                g_GATE[newglobal]  = sc[i];
            } else {
                g_MAP[oldg] = -1;
            }
        }
        __syncthreads();
        if (tid == 0){ base_g += tot_g; base_e += tot_e; }
        __syncthreads();
    }
}

// ---------------- gather kept nodes with fused norm+relu+gate (layers 1,2) ------
__global__ void k_gather_norm(const float* __restrict__ gw, const float* __restrict__ gb,
                              const float* __restrict__ ga,
                              int tot_new, int n, int f){
    int per = f >> 2;
    size_t idx = (size_t)blockIdx.x*blockDim.x + threadIdx.x;
    if (idx >= (size_t)tot_new*per) return;
    int j  = (int)(idx / per);
    int fc = (int)(idx % per)*4;
    int old = g_PERMG[j];
    int g = old / n;
    float gv = g_GATE[j];
    float4 v  = *(const float4*)&g_AGG[(size_t)old*f + fc];
    float4 mu = *(const float4*)&g_MU[g*256 + fc];
    float4 rs = *(const float4*)&g_RS[g*256 + fc];
    float4 w  = *(const float4*)&gw[fc];
    float4 b  = *(const float4*)&gb[fc];
    float4 a  = *(const float4*)&ga[fc];
    float4 o;
    o.x = fmaxf(w.x*(v.x - a.x*mu.x)*rs.x + b.x, 0.f)*gv;
    o.y = fmaxf(w.y*(v.y - a.y*mu.y)*rs.y + b.y, 0.f)*gv;
    o.z = fmaxf(w.z*(v.z - a.z*mu.z)*rs.z + b.z, 0.f)*gv;
    o.w = fmaxf(w.w*(v.w - a.w*mu.w)*rs.w + b.w, 0.f)*gv;
    *(float4*)&g_X[(size_t)j*f + fc] = o;
}

// ---------------- remap + compact edges + count next in-degrees ----------------
__global__ void k_remap(int cur){
    int e = blockIdx.x*blockDim.x + threadIdx.x;
    if (e >= g_ECNT[cur]) return;
    int s = g_MAP[g_ESRC[cur][e]];
    int d = g_MAP[g_EDST[cur][e]];
    if (s >= 0 && d >= 0){
        int p = atomicAdd(&g_ECNT[cur^1], 1);
        g_ESRC[cur^1][p] = s;
        g_EDST[cur^1][p] = d;
        atomicAdd(&g_CNT[d], 1);
    }
}

// ---------------- fused L3 gather + readout (4-way parallel partials) -----------
__global__ void k_readout(const float* __restrict__ gw, const float* __restrict__ gb,
                          const float* __restrict__ ga, int n){
    int gg = blockIdx.x;
    int cc = blockIdx.y;          // chunk 0..3 (128 rows each)
    int f  = threadIdx.x;
    float w = gw[f], b = gb[f], a = ga[f];
    float mu = g_MU[gg*256 + f], rs = g_RS[gg*256 + f];
    float s = 0.f, mx = -INFINITY;
    for (int i = cc*128; i < (cc+1)*128; i++){
        int j = gg*512 + i;
        int old = g_PERMG[j];
        float gv = g_GATE[j];
        float v = g_AGG[(size_t)old*256 + f];
        float x = fmaxf(w*(v - a*mu)*rs + b, 0.f)*gv;
        s += x;
        mx = fmaxf(mx, x);
    }
    g_PMEAN[(gg*4 + cc)*256 + f] = s;   // raw partial sum
    g_PMAX [(gg*4 + cc)*256 + f] = mx;
}

__global__ void k_final(float* __restrict__ out){
    int idx = blockIdx.x*blockDim.x + threadIdx.x;
    if (idx >= BATCH*512) return;
    int b = idx / 512, c = idx % 512;
    float acc = 0.f;
    if (c < 256){
        for (int t = 0; t < TS; t++){
            int gg = t*BATCH + b;
            float s = 0.f;
            #pragma unroll
            for (int cc = 0; cc < 4; cc++) s += g_PMEAN[(gg*4 + cc)*256 + c];
            acc += s*(1.f/512.f);
        }
    } else {
        int f = c - 256;
        for (int t = 0; t < TS; t++){
            int gg = t*BATCH + b;
            float mx = -INFINITY;
            #pragma unroll
            for (int cc = 0; cc < 4; cc++) mx = fmaxf(mx, g_PMAX[(gg*4 + cc)*256 + f]);
            acc += mx;
        }
    }
    out[idx] = acc*(1.f/(float)TS);
}

// ---------------- host orchestration ----------------
extern "C" void kernel_launch(void* const* d_in, const int* in_sizes, int n_in,
                              void* d_out, int out_size){
    const float* x_seq = (const float*)d_in[0];
    const int*   ei    = (const int*)  d_in[1];
    const float* W [3] = {(const float*)d_in[2],  (const float*)d_in[4],  (const float*)d_in[6]};
    const float* bb[3] = {(const float*)d_in[3],  (const float*)d_in[5],  (const float*)d_in[7]};
    const float* gw[3] = {(const float*)d_in[8],  (const float*)d_in[11], (const float*)d_in[14]};
    const float* gb[3] = {(const float*)d_in[9],  (const float*)d_in[12], (const float*)d_in[15]};
    const float* ga[3] = {(const float*)d_in[10], (const float*)d_in[13], (const float*)d_in[16]};
    const float* pw[3] = {(const float*)d_in[17], (const float*)d_in[18], (const float*)d_in[19]};
    float* out = (float*)d_out;

    float *pS, *pX, *pAGG;
    int *pCNT;
    cudaGetSymbolAddress((void**)&pS,   g_S);
    cudaGetSymbolAddress((void**)&pX,   g_X);
    cudaGetSymbolAddress((void**)&pAGG, g_AGG);
    cudaGetSymbolAddress((void**)&pCNT, g_CNT);

    static cudaStream_t s2 = nullptr;
    static cudaEvent_t evF[2], evJ[2];
    if (!s2){
        cudaStreamCreate(&s2);
        for (int i = 0; i < 2; i++){
            cudaEventCreateWithFlags(&evF[i], cudaEventDisableTiming);
            cudaEventCreateWithFlags(&evJ[i], cudaEventDisableTiming);
        }
    }

    const int nin [3] = {4096, 2048, 1024};
    const int nk  [3] = {2048, 1024, 512};
    const int fin [3] = {100, 128, 128};
    const int fout[3] = {128, 128, 256};

    k_zeroi<<<(NG*NPG + 255)/256, 256>>>(pCNT, NG*NPG);
    k_edge_init<<<NEDGE/256, 256>>>(ei);
    k_scan1 <<<NG*NPG/512, 512>>>(NG*NPG);
    k_scan3d<<<NG*NPG/512, 512>>>(NG*NPG);
    k_fill  <<<NEDGE/256, 256>>>(0);

    const float* A = x_seq;
    for (int l = 0; l < 3; l++){
        int n = nin[l], k = nk[l], fi = fin[l], fo = fout[l];
        int ntot = NG * n;
        int cur = l & 1, nxt = cur ^ 1;
        int wpn = (fi + 127)/128;

        k_aggregate<<<ntot*wpn/8, 256>>>(A, ntot, fi, wpn);
        k_gemm_tc<<<dim3(fo/128, ntot/128), 256>>>(pS, W[l], bb[l], pAGG, ntot, fo, fi, n);

        k_finstats<<<(NG*256 + 255)/256, 256>>>(ga[l], pw[l], n, fo);
        k_score<<<ntot/8, 256>>>(gw[l], gb[l], ga[l], pw[l], ntot, n, fo);

        k_topk<<<NG, 512>>>(n, k, nxt);

        if (l < 2){
            int tot_new = NG * k;
            int nb2 = tot_new / 512;
            cudaEventRecord(evF[l], 0);
            cudaStreamWaitEvent(s2, evF[l], 0);
            k_zeroi <<<(tot_new + 255)/256, 256, 0, s2>>>(pCNT, tot_new);
            k_remap <<<NEDGE/256, 256, 0, s2>>>(cur);
            k_scan1 <<<nb2, 512, 0, s2>>>(tot_new);
            k_scan3d<<<nb2, 512, 0, s2>>>(tot_new);
            k_fill  <<<NEDGE/256, 256, 0, s2>>>(nxt);
            cudaEventRecord(evJ[l], s2);

            k_gather_norm<<<(int)(((size_t)tot_new*(fo/4) + 255)/256), 256>>>(gw[l], gb[l], ga[l], tot_new, n, fo);
            cudaStreamWaitEvent(0, evJ[l], 0);
            A = pX;
        }
    }

    k_readout<<<dim3(NG, 4), 256>>>(gw[2], gb[2], ga[2], nin[2]);
    k_final<<<(BATCH*512 + 255)/256, 256>>>(out);
}